// round 1
// baseline (speedup 1.0000x reference)
#include <cuda_runtime.h>
#include <math.h>

// Problem constants
#define BB    4
#define TT    2048
#define DIM   512
#define NH    8
#define DH    64
#define MROWS (BB*TT)      // 8192
#define CHUNK 128
#define NCH   (TT/CHUNK)   // 16
#define WIN   256
#define TBLK  64           // retention t-tile
#define SBLK  32           // retention s-chunk

// log2(0.9)
#define L2DECAY (-0.15200309344504997f)

// Scratch (allocation-free rule: __device__ globals)
__device__ float g_a [MROWS*DIM];
__device__ float g_b [MROWS*DIM];
__device__ float g_g [MROWS*DIM];
__device__ float g_hg[MROWS*DIM];
__device__ float g_cA  [BB*NCH*DIM];
__device__ float g_cB  [BB*NCH*DIM];
__device__ float g_pref[BB*NCH*DIM];

// ---------------------------------------------------------------------------
// Generic 8192x512x512 f32 GEMM: C = act(X @ W + bias)
// act: 0 = none, 1 = sigmoid
// Tile 64x64, BK=16, 256 threads, 4x4 per thread.
// ---------------------------------------------------------------------------
__global__ __launch_bounds__(256) void gemm512(
    const float* __restrict__ X, const float* __restrict__ W,
    const float* __restrict__ bias, float* __restrict__ C, int act)
{
    __shared__ float Xs[16][64];   // [k][m]
    __shared__ float Ws[16][64];   // [k][n]

    const int tid = threadIdx.x;
    const int tx  = tid & 15;      // n group
    const int ty  = tid >> 4;      // m group
    const int m0  = blockIdx.y * 64;
    const int n0  = blockIdx.x * 64;

    // X load mapping: 64 rows x 16 k, float4 along k
    const int lr = tid >> 2;           // 0..63
    const int lk = (tid & 3) * 4;      // 0,4,8,12
    // W load mapping: 16 k-rows x 64 n, float4 along n
    const int wk = tid >> 4;           // 0..15
    const int wn = (tid & 15) * 4;     // 0..60

    float acc[4][4];
#pragma unroll
    for (int i = 0; i < 4; i++)
#pragma unroll
        for (int j = 0; j < 4; j++) acc[i][j] = 0.0f;

    for (int k0 = 0; k0 < DIM; k0 += 16) {
        float4 xv = *(const float4*)&X[(size_t)(m0 + lr) * DIM + k0 + lk];
        Xs[lk + 0][lr] = xv.x;
        Xs[lk + 1][lr] = xv.y;
        Xs[lk + 2][lr] = xv.z;
        Xs[lk + 3][lr] = xv.w;
        *(float4*)&Ws[wk][wn] = *(const float4*)&W[(size_t)(k0 + wk) * DIM + n0 + wn];
        __syncthreads();
#pragma unroll
        for (int kk = 0; kk < 16; kk++) {
            float4 av = *(const float4*)&Xs[kk][ty * 4];
            float4 bv = *(const float4*)&Ws[kk][tx * 4];
            float a4[4] = {av.x, av.y, av.z, av.w};
            float b4[4] = {bv.x, bv.y, bv.z, bv.w};
#pragma unroll
            for (int i = 0; i < 4; i++)
#pragma unroll
                for (int j = 0; j < 4; j++)
                    acc[i][j] = fmaf(a4[i], b4[j], acc[i][j]);
        }
        __syncthreads();
    }

#pragma unroll
    for (int i = 0; i < 4; i++) {
        const int m = m0 + ty * 4 + i;
#pragma unroll
        for (int j = 0; j < 4; j++) {
            const int n = n0 + tx * 4 + j;
            float v = acc[i][j] + bias[n];
            if (act) v = 1.0f / (1.0f + __expf(-v));
            C[(size_t)m * DIM + n] = v;
        }
    }
}

// ---------------------------------------------------------------------------
// Chunked linear scan: h_t = a_t*h_{t-1} + b_t, h_{-1}=0, per (batch, dim).
// ---------------------------------------------------------------------------
__global__ __launch_bounds__(512) void scan_chunks()
{
    const int d  = threadIdx.x;
    const int c  = blockIdx.x;
    const int bb = blockIdx.y;
    size_t base = ((size_t)(bb * TT + c * CHUNK)) * DIM + d;
    float A = 1.0f, h = 0.0f;
#pragma unroll 4
    for (int t = 0; t < CHUNK; t++) {
        float av = g_a[base + (size_t)t * DIM];
        float bv = g_b[base + (size_t)t * DIM];
        h = fmaf(av, h, bv);
        A *= av;
    }
    g_cA[(bb * NCH + c) * DIM + d] = A;
    g_cB[(bb * NCH + c) * DIM + d] = h;
}

__global__ __launch_bounds__(512) void scan_carry()
{
    const int d  = threadIdx.x;
    const int bb = blockIdx.x;
    float h = 0.0f;
#pragma unroll
    for (int c = 0; c < NCH; c++) {
        const int idx = (bb * NCH + c) * DIM + d;
        g_pref[idx] = h;
        h = fmaf(g_cA[idx], h, g_cB[idx]);
    }
}

__global__ __launch_bounds__(512) void scan_apply()
{
    const int d  = threadIdx.x;
    const int c  = blockIdx.x;
    const int bb = blockIdx.y;
    size_t base = ((size_t)(bb * TT + c * CHUNK)) * DIM + d;
    float h = g_pref[(bb * NCH + c) * DIM + d];
#pragma unroll 4
    for (int t = 0; t < CHUNK; t++) {
        float av = g_a[base + (size_t)t * DIM];
        float bv = g_b[base + (size_t)t * DIM];
        h = fmaf(av, h, bv);
        g_hg[base + (size_t)t * DIM] = h * g_g[base + (size_t)t * DIM];
    }
}

// ---------------------------------------------------------------------------
// Windowed retention: out[b,t,h*64+d] += sum_{s in [t-WIN, t]} (q_t.k_s) * 0.9^(t-s) * v_s[d]
// Block: one (b, h, 64-t tile). 256 threads. s processed in 32-chunks.
// ---------------------------------------------------------------------------
__global__ __launch_bounds__(256) void retention(
    const float* __restrict__ q, const float* __restrict__ k,
    const float* __restrict__ v, float* __restrict__ out)
{
    __shared__ float QsT[DH][TBLK];       // [dim][t]   64x64
    __shared__ float KsT[DH][SBLK];       // [dim][s]   64x32
    __shared__ float Vs [SBLK][DH];       // [s][dim]   32x64
    __shared__ float Ss [TBLK][SBLK + 1]; // [t][s]     64x33

    const int tid = threadIdx.x;
    const int t0  = blockIdx.x * TBLK;
    const int hh  = blockIdx.y;
    const int bb  = blockIdx.z;

    const float* qb = q + (size_t)bb * TT * DIM + hh * DH;
    const float* kb = k + (size_t)bb * TT * DIM + hh * DH;
    const float* vb = v + (size_t)bb * TT * DIM + hh * DH;

    // --- load Q tile (transposed into smem) ---
    {
        const int qr = tid >> 2;          // 0..63 (t)
        const int qc = (tid & 3) * 16;    // dim offset
#pragma unroll
        for (int j = 0; j < 16; j += 4) {
            float4 t4 = *(const float4*)&qb[(size_t)(t0 + qr) * DIM + qc + j];
            QsT[qc + j + 0][qr] = t4.x;
            QsT[qc + j + 1][qr] = t4.y;
            QsT[qc + j + 2][qr] = t4.z;
            QsT[qc + j + 3][qr] = t4.w;
        }
    }

    const int ty = tid >> 4;   // 0..15
    const int tx = tid & 15;   // 0..15

    float oacc[4][4];
#pragma unroll
    for (int i = 0; i < 4; i++)
#pragma unroll
        for (int j = 0; j < 4; j++) oacc[i][j] = 0.0f;

    const int sBeg = (t0 >= WIN) ? (t0 - WIN) : 0;
    const int sEnd = t0 + TBLK;    // exclusive

    for (int s0 = sBeg; s0 < sEnd; s0 += SBLK) {
        // --- load K (transposed) and V (row-major) chunks ---
        {
            const int kr = tid >> 3;          // 0..31 (s)
            const int kc = (tid & 7) * 8;     // dim offset
#pragma unroll
            for (int j = 0; j < 8; j += 4) {
                float4 t4 = *(const float4*)&kb[(size_t)(s0 + kr) * DIM + kc + j];
                KsT[kc + j + 0][kr] = t4.x;
                KsT[kc + j + 1][kr] = t4.y;
                KsT[kc + j + 2][kr] = t4.z;
                KsT[kc + j + 3][kr] = t4.w;
                float4 v4 = *(const float4*)&vb[(size_t)(s0 + kr) * DIM + kc + j];
                *(float4*)&Vs[kr][kc + j] = v4;
            }
        }
        __syncthreads();

        // --- S[64x32] = Q . K^T ---
        float sreg[4][2];
#pragma unroll
        for (int i = 0; i < 4; i++) { sreg[i][0] = 0.0f; sreg[i][1] = 0.0f; }
#pragma unroll
        for (int kk = 0; kk < DH; kk++) {
            float4 av = *(const float4*)&QsT[kk][ty * 4];
            float2 bv = *(const float2*)&KsT[kk][tx * 2];
            float a4[4] = {av.x, av.y, av.z, av.w};
#pragma unroll
            for (int i = 0; i < 4; i++) {
                sreg[i][0] = fmaf(a4[i], bv.x, sreg[i][0]);
                sreg[i][1] = fmaf(a4[i], bv.y, sreg[i][1]);
            }
        }
        // decay + causal mask, store to smem
#pragma unroll
        for (int i = 0; i < 4; i++) {
            const int t = t0 + ty * 4 + i;
#pragma unroll
            for (int j = 0; j < 2; j++) {
                const int s = s0 + tx * 2 + j;
                const int delta = t - s;
                float w = (delta >= 0) ? exp2f((float)delta * L2DECAY) : 0.0f;
                Ss[ty * 4 + i][tx * 2 + j] = sreg[i][j] * w;
            }
        }
        __syncthreads();

        // --- O[64x64] += S . V ---
#pragma unroll
        for (int s = 0; s < SBLK; s++) {
            float a0 = Ss[ty * 4 + 0][s];
            float a1 = Ss[ty * 4 + 1][s];
            float a2 = Ss[ty * 4 + 2][s];
            float a3 = Ss[ty * 4 + 3][s];
            float4 bv = *(const float4*)&Vs[s][tx * 4];
            float b4[4] = {bv.x, bv.y, bv.z, bv.w};
            float a4[4] = {a0, a1, a2, a3};
#pragma unroll
            for (int i = 0; i < 4; i++)
#pragma unroll
                for (int j = 0; j < 4; j++)
                    oacc[i][j] = fmaf(a4[i], b4[j], oacc[i][j]);
        }
        __syncthreads();
    }

    // --- accumulate into out (m_out already there) ---
#pragma unroll
    for (int i = 0; i < 4; i++) {
        const int t = t0 + ty * 4 + i;
        float* orow = out + ((size_t)bb * TT + t) * DIM + hh * DH + tx * 4;
#pragma unroll
        for (int j = 0; j < 4; j++)
            orow[j] += oacc[i][j];
    }
}

// ---------------------------------------------------------------------------
extern "C" void kernel_launch(void* const* d_in, const int* in_sizes, int n_in,
                              void* d_out, int out_size)
{
    const float* q  = (const float*)d_in[0];
    const float* k  = (const float*)d_in[1];
    const float* v  = (const float*)d_in[2];
    const float* Wa = (const float*)d_in[3];
    const float* ba = (const float*)d_in[4];
    const float* Wb = (const float*)d_in[5];
    const float* bb = (const float*)d_in[6];
    const float* Wg = (const float*)d_in[7];
    const float* bg = (const float*)d_in[8];
    const float* Wo = (const float*)d_in[9];
    const float* bo = (const float*)d_in[10];
    float* out = (float*)d_out;

    float *pa, *pb, *pg, *phg;
    cudaGetSymbolAddress((void**)&pa,  g_a);
    cudaGetSymbolAddress((void**)&pb,  g_b);
    cudaGetSymbolAddress((void**)&pg,  g_g);
    cudaGetSymbolAddress((void**)&phg, g_hg);

    dim3 gg(DIM / 64, MROWS / 64);
    gemm512<<<gg, 256>>>(q, Wa, ba, pa, 1);
    gemm512<<<gg, 256>>>(q, Wb, bb, pb, 0);
    gemm512<<<gg, 256>>>(q, Wg, bg, pg, 1);

    scan_chunks<<<dim3(NCH, BB), 512>>>();
    scan_carry<<<BB, 512>>>();
    scan_apply<<<dim3(NCH, BB), 512>>>();

    gemm512<<<gg, 256>>>(phg, Wo, bo, out, 0);

    retention<<<dim3(TT / TBLK, NH, BB), 256>>>(q, k, v, out);
}

// round 3
// speedup vs baseline: 1.7543x; 1.7543x over previous
#include <cuda_runtime.h>
#include <math.h>
#include <stdint.h>

// Problem constants
#define BB    4
#define TT    2048
#define DIM   512
#define NH    8
#define DH    64
#define MROWS (BB*TT)      // 8192
#define CHUNK 64
#define NCH   (TT/CHUNK)   // 32
#define WIN   256
#define TBLK  64           // retention t-tile
#define SBLK  32           // retention s-chunk

#define L2DECAY (-0.15200309344504997f)   // log2(0.9)

// Scratch (allocation-free rule: __device__ globals)
__device__ float g_a [MROWS*DIM];
__device__ float g_b [MROWS*DIM];
__device__ float g_g [MROWS*DIM];
__device__ float g_hg[MROWS*DIM];
__device__ float g_cA  [BB*NCH*DIM];
__device__ float g_cB  [BB*NCH*DIM];
__device__ float g_pref[BB*NCH*DIM];
__device__ float g_Wt[4][DIM*DIM];   // transposed weights [n][k]

// ---------------------------------------------------------------------------
// Weight transpose: Wt[n][k] = W[k][n]  (512x512)
// ---------------------------------------------------------------------------
__global__ __launch_bounds__(256) void transposeW(
    const float* __restrict__ W, float* __restrict__ Wt)
{
    __shared__ float t[32][33];
    const int tx = threadIdx.x, ty = threadIdx.y;   // 32 x 8
    const int k0 = blockIdx.x * 32, n0 = blockIdx.y * 32;
#pragma unroll
    for (int j = 0; j < 32; j += 8)
        t[ty + j][tx] = W[(size_t)(k0 + ty + j) * DIM + n0 + tx];
    __syncthreads();
#pragma unroll
    for (int j = 0; j < 32; j += 8)
        Wt[(size_t)(n0 + ty + j) * DIM + k0 + tx] = t[tx][ty + j];
}

// ---------------------------------------------------------------------------
// tf32 mma.sync GEMM: C[8192x512] = act(X @ Wt^T + bias), Wt is [N,K].
// CTA tile 128x128, 8 warps (warp tile 32x64), BK=32, double-buffered smem.
// ---------------------------------------------------------------------------
#define SROW   36                      // padded row stride (floats)
#define ABUF   (128 * SROW)            // 4608 floats per operand tile
#define BUFSZ  (2 * ABUF)              // A + B per buffer
#define GSMEM_BYTES (2 * BUFSZ * 4)    // 73728 bytes

__device__ __forceinline__ uint32_t f2tf32(float x) {
    uint32_t u;
    asm("cvt.rna.tf32.f32 %0, %1;" : "=r"(u) : "f"(x));
    return u;
}

__device__ __forceinline__ void mma_tf32(
    float c[4], const uint32_t a[4], const uint32_t b[2])
{
    asm volatile(
        "mma.sync.aligned.m16n8k8.row.col.f32.tf32.tf32.f32 "
        "{%0,%1,%2,%3}, {%4,%5,%6,%7}, {%8,%9}, {%0,%1,%2,%3};"
        : "+f"(c[0]), "+f"(c[1]), "+f"(c[2]), "+f"(c[3])
        : "r"(a[0]), "r"(a[1]), "r"(a[2]), "r"(a[3]), "r"(b[0]), "r"(b[1]));
}

__global__ __launch_bounds__(256) void gemm_mma(
    const float* __restrict__ X, const float* __restrict__ Wt,
    const float* __restrict__ bias, float* __restrict__ C, int act)
{
    extern __shared__ uint32_t sm[];
    const int tid   = threadIdx.x;
    const int lane  = tid & 31;
    const int wid   = tid >> 5;
    const int g     = lane >> 2;
    const int t4    = lane & 3;
    const int warpM = wid & 3;         // 4 m-strips of 32
    const int warpN = wid >> 2;        // 2 n-strips of 64
    const int m0 = blockIdx.y * 128;
    const int n0 = blockIdx.x * 128;

    // staging mapping: row 0..127, 16 consecutive k-floats
    const int srow = tid >> 1;
    const int scol = (tid & 1) * 16;

    float c[2][8][4];
#pragma unroll
    for (int mt = 0; mt < 2; mt++)
#pragma unroll
        for (int nt = 0; nt < 8; nt++)
#pragma unroll
            for (int r = 0; r < 4; r++) c[mt][nt][r] = 0.0f;

    uint32_t ra[16], rb[16];

    // load chunk 0 into regs (converted to tf32)
#pragma unroll
    for (int j = 0; j < 4; j++) {
        float4 xa = *(const float4*)&X [(size_t)(m0 + srow) * DIM + scol + 4*j];
        float4 xb = *(const float4*)&Wt[(size_t)(n0 + srow) * DIM + scol + 4*j];
        ra[4*j+0] = f2tf32(xa.x); ra[4*j+1] = f2tf32(xa.y);
        ra[4*j+2] = f2tf32(xa.z); ra[4*j+3] = f2tf32(xa.w);
        rb[4*j+0] = f2tf32(xb.x); rb[4*j+1] = f2tf32(xb.y);
        rb[4*j+2] = f2tf32(xb.z); rb[4*j+3] = f2tf32(xb.w);
    }
    // store to buffer 0
    {
        uint32_t* dA = sm + 0 * BUFSZ + srow * SROW + scol;
        uint32_t* dB = dA + ABUF;
#pragma unroll
        for (int j = 0; j < 4; j++) {
            *(uint4*)&dA[4*j] = make_uint4(ra[4*j], ra[4*j+1], ra[4*j+2], ra[4*j+3]);
            *(uint4*)&dB[4*j] = make_uint4(rb[4*j], rb[4*j+1], rb[4*j+2], rb[4*j+3]);
        }
    }
    __syncthreads();

    for (int ch = 0; ch < DIM / 32; ch++) {
        const int cur = ch & 1;
        // prefetch next chunk into regs (overlaps with compute below)
        if (ch + 1 < DIM / 32) {
            const int k0 = (ch + 1) * 32;
#pragma unroll
            for (int j = 0; j < 4; j++) {
                float4 xa = *(const float4*)&X [(size_t)(m0 + srow) * DIM + k0 + scol + 4*j];
                float4 xb = *(const float4*)&Wt[(size_t)(n0 + srow) * DIM + k0 + scol + 4*j];
                ra[4*j+0] = f2tf32(xa.x); ra[4*j+1] = f2tf32(xa.y);
                ra[4*j+2] = f2tf32(xa.z); ra[4*j+3] = f2tf32(xa.w);
                rb[4*j+0] = f2tf32(xb.x); rb[4*j+1] = f2tf32(xb.y);
                rb[4*j+2] = f2tf32(xb.z); rb[4*j+3] = f2tf32(xb.w);
            }
        }

        // compute on buffer cur
        const uint32_t* smA = sm + cur * BUFSZ;
        const uint32_t* smB = smA + ABUF;
#pragma unroll
        for (int kk = 0; kk < 4; kk++) {
            const int col = kk * 8 + t4;
            uint32_t af[2][4], bf[8][2];
#pragma unroll
            for (int mt = 0; mt < 2; mt++) {
                const int r0 = (warpM * 32 + mt * 16 + g) * SROW;
                af[mt][0] = smA[r0 + col];
                af[mt][1] = smA[r0 + 8 * SROW + col];
                af[mt][2] = smA[r0 + col + 4];
                af[mt][3] = smA[r0 + 8 * SROW + col + 4];
            }
#pragma unroll
            for (int nt = 0; nt < 8; nt++) {
                const int rn = (warpN * 64 + nt * 8 + g) * SROW;
                bf[nt][0] = smB[rn + col];
                bf[nt][1] = smB[rn + col + 4];
            }
#pragma unroll
            for (int mt = 0; mt < 2; mt++)
#pragma unroll
                for (int nt = 0; nt < 8; nt++)
                    mma_tf32(c[mt][nt], af[mt], bf[nt]);
        }

        // store prefetched chunk to the other buffer
        if (ch + 1 < DIM / 32) {
            uint32_t* dA = sm + (cur ^ 1) * BUFSZ + srow * SROW + scol;
            uint32_t* dB = dA + ABUF;
#pragma unroll
            for (int j = 0; j < 4; j++) {
                *(uint4*)&dA[4*j] = make_uint4(ra[4*j], ra[4*j+1], ra[4*j+2], ra[4*j+3]);
                *(uint4*)&dB[4*j] = make_uint4(rb[4*j], rb[4*j+1], rb[4*j+2], rb[4*j+3]);
            }
        }
        __syncthreads();
    }

    // epilogue
#pragma unroll
    for (int mt = 0; mt < 2; mt++) {
#pragma unroll
        for (int nt = 0; nt < 8; nt++) {
            const int row  = m0 + warpM * 32 + mt * 16 + g;
            const int coln = n0 + warpN * 64 + nt * 8 + t4 * 2;
            const float b0 = bias[coln], b1 = bias[coln + 1];
            float v0 = c[mt][nt][0] + b0;
            float v1 = c[mt][nt][1] + b1;
            float v2 = c[mt][nt][2] + b0;
            float v3 = c[mt][nt][3] + b1;
            if (act) {
                v0 = 1.0f / (1.0f + __expf(-v0));
                v1 = 1.0f / (1.0f + __expf(-v1));
                v2 = 1.0f / (1.0f + __expf(-v2));
                v3 = 1.0f / (1.0f + __expf(-v3));
            }
            *(float2*)&C[(size_t)row * DIM + coln]       = make_float2(v0, v1);
            *(float2*)&C[(size_t)(row + 8) * DIM + coln] = make_float2(v2, v3);
        }
    }
}

// ---------------------------------------------------------------------------
// Chunked linear scan: h_t = a_t*h_{t-1} + b_t, h_{-1}=0, per (batch, dim).
// ---------------------------------------------------------------------------
__global__ __launch_bounds__(512) void scan_chunks()
{
    const int d  = threadIdx.x;
    const int c  = blockIdx.x;
    const int bb = blockIdx.y;
    size_t base = ((size_t)(bb * TT + c * CHUNK)) * DIM + d;
    float A = 1.0f, h = 0.0f;
#pragma unroll 4
    for (int t = 0; t < CHUNK; t++) {
        float av = g_a[base + (size_t)t * DIM];
        float bv = g_b[base + (size_t)t * DIM];
        h = fmaf(av, h, bv);
        A *= av;
    }
    g_cA[(bb * NCH + c) * DIM + d] = A;
    g_cB[(bb * NCH + c) * DIM + d] = h;
}

__global__ __launch_bounds__(512) void scan_carry()
{
    const int d  = threadIdx.x;
    const int bb = blockIdx.x;
    float h = 0.0f;
#pragma unroll
    for (int c = 0; c < NCH; c++) {
        const int idx = (bb * NCH + c) * DIM + d;
        g_pref[idx] = h;
        h = fmaf(g_cA[idx], h, g_cB[idx]);
    }
}

__global__ __launch_bounds__(512) void scan_apply()
{
    const int d  = threadIdx.x;
    const int c  = blockIdx.x;
    const int bb = blockIdx.y;
    size_t base = ((size_t)(bb * TT + c * CHUNK)) * DIM + d;
    float h = g_pref[(bb * NCH + c) * DIM + d];
#pragma unroll 4
    for (int t = 0; t < CHUNK; t++) {
        float av = g_a[base + (size_t)t * DIM];
        float bv = g_b[base + (size_t)t * DIM];
        h = fmaf(av, h, bv);
        g_hg[base + (size_t)t * DIM] = h * g_g[base + (size_t)t * DIM];
    }
}

// ---------------------------------------------------------------------------
// Windowed retention (DECAY^256 ~ 2e-12 -> truncated causal window)
// ---------------------------------------------------------------------------
__global__ __launch_bounds__(256) void retention(
    const float* __restrict__ q, const float* __restrict__ k,
    const float* __restrict__ v, float* __restrict__ out)
{
    __shared__ float QsT[DH][TBLK];
    __shared__ float KsT[DH][SBLK];
    __shared__ float Vs [SBLK][DH];
    __shared__ float Ss [TBLK][SBLK + 1];

    const int tid = threadIdx.x;
    const int t0  = blockIdx.x * TBLK;
    const int hh  = blockIdx.y;
    const int bb  = blockIdx.z;

    const float* qb = q + (size_t)bb * TT * DIM + hh * DH;
    const float* kb = k + (size_t)bb * TT * DIM + hh * DH;
    const float* vb = v + (size_t)bb * TT * DIM + hh * DH;

    {
        const int qr = tid >> 2;
        const int qc = (tid & 3) * 16;
#pragma unroll
        for (int j = 0; j < 16; j += 4) {
            float4 t4 = *(const float4*)&qb[(size_t)(t0 + qr) * DIM + qc + j];
            QsT[qc + j + 0][qr] = t4.x;
            QsT[qc + j + 1][qr] = t4.y;
            QsT[qc + j + 2][qr] = t4.z;
            QsT[qc + j + 3][qr] = t4.w;
        }
    }

    const int ty = tid >> 4;
    const int tx = tid & 15;

    float oacc[4][4];
#pragma unroll
    for (int i = 0; i < 4; i++)
#pragma unroll
        for (int j = 0; j < 4; j++) oacc[i][j] = 0.0f;

    const int sBeg = (t0 >= WIN) ? (t0 - WIN) : 0;
    const int sEnd = t0 + TBLK;

    for (int s0 = sBeg; s0 < sEnd; s0 += SBLK) {
        {
            const int kr = tid >> 3;
            const int kc = (tid & 7) * 8;
#pragma unroll
            for (int j = 0; j < 8; j += 4) {
                float4 t4 = *(const float4*)&kb[(size_t)(s0 + kr) * DIM + kc + j];
                KsT[kc + j + 0][kr] = t4.x;
                KsT[kc + j + 1][kr] = t4.y;
                KsT[kc + j + 2][kr] = t4.z;
                KsT[kc + j + 3][kr] = t4.w;
                float4 v4 = *(const float4*)&vb[(size_t)(s0 + kr) * DIM + kc + j];
                *(float4*)&Vs[kr][kc + j] = v4;
            }
        }
        __syncthreads();

        float sreg[4][2];
#pragma unroll
        for (int i = 0; i < 4; i++) { sreg[i][0] = 0.0f; sreg[i][1] = 0.0f; }
#pragma unroll
        for (int kk = 0; kk < DH; kk++) {
            float4 av = *(const float4*)&QsT[kk][ty * 4];
            float2 bv = *(const float2*)&KsT[kk][tx * 2];
            float a4[4] = {av.x, av.y, av.z, av.w};
#pragma unroll
            for (int i = 0; i < 4; i++) {
                sreg[i][0] = fmaf(a4[i], bv.x, sreg[i][0]);
                sreg[i][1] = fmaf(a4[i], bv.y, sreg[i][1]);
            }
        }
#pragma unroll
        for (int i = 0; i < 4; i++) {
            const int t = t0 + ty * 4 + i;
#pragma unroll
            for (int j = 0; j < 2; j++) {
                const int s = s0 + tx * 2 + j;
                const int delta = t - s;
                float w = (delta >= 0) ? exp2f((float)delta * L2DECAY) : 0.0f;
                Ss[ty * 4 + i][tx * 2 + j] = sreg[i][j] * w;
            }
        }
        __syncthreads();

#pragma unroll
        for (int s = 0; s < SBLK; s++) {
            float a0 = Ss[ty * 4 + 0][s];
            float a1 = Ss[ty * 4 + 1][s];
            float a2 = Ss[ty * 4 + 2][s];
            float a3 = Ss[ty * 4 + 3][s];
            float4 bv = *(const float4*)&Vs[s][tx * 4];
            float b4[4] = {bv.x, bv.y, bv.z, bv.w};
            float a4[4] = {a0, a1, a2, a3};
#pragma unroll
            for (int i = 0; i < 4; i++)
#pragma unroll
                for (int j = 0; j < 4; j++)
                    oacc[i][j] = fmaf(a4[i], b4[j], oacc[i][j]);
        }
        __syncthreads();
    }

#pragma unroll
    for (int i = 0; i < 4; i++) {
        const int t = t0 + ty * 4 + i;
        float* orow = out + ((size_t)bb * TT + t) * DIM + hh * DH + tx * 4;
#pragma unroll
        for (int j = 0; j < 4; j++)
            orow[j] += oacc[i][j];
    }
}

// ---------------------------------------------------------------------------
extern "C" void kernel_launch(void* const* d_in, const int* in_sizes, int n_in,
                              void* d_out, int out_size)
{
    const float* q  = (const float*)d_in[0];
    const float* k  = (const float*)d_in[1];
    const float* v  = (const float*)d_in[2];
    const float* Wa = (const float*)d_in[3];
    const float* ba = (const float*)d_in[4];
    const float* Wb = (const float*)d_in[5];
    const float* bb = (const float*)d_in[6];
    const float* Wg = (const float*)d_in[7];
    const float* bg = (const float*)d_in[8];
    const float* Wo = (const float*)d_in[9];
    const float* bo = (const float*)d_in[10];
    float* out = (float*)d_out;

    float *pa, *pb, *pg, *phg, *pwt;
    cudaGetSymbolAddress((void**)&pa,  g_a);
    cudaGetSymbolAddress((void**)&pb,  g_b);
    cudaGetSymbolAddress((void**)&pg,  g_g);
    cudaGetSymbolAddress((void**)&phg, g_hg);
    cudaGetSymbolAddress((void**)&pwt, g_Wt);

    cudaFuncSetAttribute(gemm_mma, cudaFuncAttributeMaxDynamicSharedMemorySize,
                         GSMEM_BYTES);

    // transpose all weights (W is [K,N] row-major; gemm wants B=[N,K] K-major)
    dim3 tgrid(DIM / 32, DIM / 32);
    dim3 tblk(32, 8);
    transposeW<<<tgrid, tblk>>>(Wa, pwt + 0 * DIM * DIM);
    transposeW<<<tgrid, tblk>>>(Wb, pwt + 1 * DIM * DIM);
    transposeW<<<tgrid, tblk>>>(Wg, pwt + 2 * DIM * DIM);
    transposeW<<<tgrid, tblk>>>(Wo, pwt + 3 * DIM * DIM);

    dim3 gg(DIM / 128, MROWS / 128);   // 4 x 64
    gemm_mma<<<gg, 256, GSMEM_BYTES>>>(q, pwt + 0 * DIM * DIM, ba, pa, 1);
    gemm_mma<<<gg, 256, GSMEM_BYTES>>>(q, pwt + 1 * DIM * DIM, bb, pb, 0);
    gemm_mma<<<gg, 256, GSMEM_BYTES>>>(q, pwt + 2 * DIM * DIM, bg, pg, 1);

    scan_chunks<<<dim3(NCH, BB), 512>>>();
    scan_carry<<<BB, 512>>>();
    scan_apply<<<dim3(NCH, BB), 512>>>();

    gemm_mma<<<gg, 256, GSMEM_BYTES>>>(phg, pwt + 3 * DIM * DIM, bo, out, 0);

    retention<<<dim3(TT / TBLK, NH, BB), 256>>>(q, k, v, out);
}

// round 4
// speedup vs baseline: 2.4967x; 1.4232x over previous
#include <cuda_runtime.h>
#include <cuda_fp16.h>
#include <math.h>
#include <stdint.h>

// Problem constants
#define BB    4
#define TT    2048
#define DIM   512
#define NH    8
#define DH    64
#define MROWS (BB*TT)      // 8192
#define CHUNK 64
#define NCH   (TT/CHUNK)   // 32
#define WIN   256
#define TBLK  64           // retention t-tile
#define SCH   64           // retention s-chunk

#define L2DECAY (-0.15200309344504997f)   // log2(0.9)
#define D8      (0.43046721f)             // 0.9^8
#define DINV    (1.1111111111111112f)     // 0.9^-1
#define DM8INV  (2.3230573202841774f)     // 0.9^-8

// Scratch (allocation-free rule: __device__ globals)
__device__ float g_a [MROWS*DIM];
__device__ float g_b [MROWS*DIM];
__device__ float g_g [MROWS*DIM];
__device__ float g_hg[MROWS*DIM];
__device__ float g_cA  [BB*NCH*DIM];
__device__ float g_cB  [BB*NCH*DIM];
__device__ float g_pref[BB*NCH*DIM];
__device__ float g_Wt[4][DIM*DIM];   // transposed weights [n][k]

// ---------------------------------------------------------------------------
// Fused weight transpose: Wt[z][n][k] = W_z[k][n]  (4 x 512x512)
// ---------------------------------------------------------------------------
__global__ __launch_bounds__(256) void transposeW4(
    const float* __restrict__ W0, const float* __restrict__ W1,
    const float* __restrict__ W2, const float* __restrict__ W3,
    float* __restrict__ Wt)
{
    __shared__ float t[32][33];
    const float* W = (blockIdx.z == 0) ? W0 : (blockIdx.z == 1) ? W1
                   : (blockIdx.z == 2) ? W2 : W3;
    float* Wtz = Wt + (size_t)blockIdx.z * DIM * DIM;
    const int tx = threadIdx.x, ty = threadIdx.y;   // 32 x 8
    const int k0 = blockIdx.x * 32, n0 = blockIdx.y * 32;
#pragma unroll
    for (int j = 0; j < 32; j += 8)
        t[ty + j][tx] = W[(size_t)(k0 + ty + j) * DIM + n0 + tx];
    __syncthreads();
#pragma unroll
    for (int j = 0; j < 32; j += 8)
        Wtz[(size_t)(n0 + ty + j) * DIM + k0 + tx] = t[tx][ty + j];
}

// ---------------------------------------------------------------------------
// tf32 mma.sync GEMM (unchanged from R3): C = act(X @ Wt^T + bias)
// ---------------------------------------------------------------------------
#define SROW   36
#define ABUF   (128 * SROW)
#define BUFSZ  (2 * ABUF)
#define GSMEM_BYTES (2 * BUFSZ * 4)

__device__ __forceinline__ uint32_t f2tf32(float x) {
    uint32_t u;
    asm("cvt.rna.tf32.f32 %0, %1;" : "=r"(u) : "f"(x));
    return u;
}

__device__ __forceinline__ void mma_tf32(
    float c[4], const uint32_t a[4], const uint32_t b[2])
{
    asm volatile(
        "mma.sync.aligned.m16n8k8.row.col.f32.tf32.tf32.f32 "
        "{%0,%1,%2,%3}, {%4,%5,%6,%7}, {%8,%9}, {%0,%1,%2,%3};"
        : "+f"(c[0]), "+f"(c[1]), "+f"(c[2]), "+f"(c[3])
        : "r"(a[0]), "r"(a[1]), "r"(a[2]), "r"(a[3]), "r"(b[0]), "r"(b[1]));
}

__global__ __launch_bounds__(256) void gemm_mma(
    const float* __restrict__ X, const float* __restrict__ Wt,
    const float* __restrict__ bias, float* __restrict__ C, int act)
{
    extern __shared__ uint32_t sm[];
    const int tid   = threadIdx.x;
    const int lane  = tid & 31;
    const int wid   = tid >> 5;
    const int g     = lane >> 2;
    const int t4    = lane & 3;
    const int warpM = wid & 3;
    const int warpN = wid >> 2;
    const int m0 = blockIdx.y * 128;
    const int n0 = blockIdx.x * 128;

    const int srow = tid >> 1;
    const int scol = (tid & 1) * 16;

    float c[2][8][4];
#pragma unroll
    for (int mt = 0; mt < 2; mt++)
#pragma unroll
        for (int nt = 0; nt < 8; nt++)
#pragma unroll
            for (int r = 0; r < 4; r++) c[mt][nt][r] = 0.0f;

    uint32_t ra[16], rb[16];

#pragma unroll
    for (int j = 0; j < 4; j++) {
        float4 xa = *(const float4*)&X [(size_t)(m0 + srow) * DIM + scol + 4*j];
        float4 xb = *(const float4*)&Wt[(size_t)(n0 + srow) * DIM + scol + 4*j];
        ra[4*j+0] = f2tf32(xa.x); ra[4*j+1] = f2tf32(xa.y);
        ra[4*j+2] = f2tf32(xa.z); ra[4*j+3] = f2tf32(xa.w);
        rb[4*j+0] = f2tf32(xb.x); rb[4*j+1] = f2tf32(xb.y);
        rb[4*j+2] = f2tf32(xb.z); rb[4*j+3] = f2tf32(xb.w);
    }
    {
        uint32_t* dA = sm + 0 * BUFSZ + srow * SROW + scol;
        uint32_t* dB = dA + ABUF;
#pragma unroll
        for (int j = 0; j < 4; j++) {
            *(uint4*)&dA[4*j] = make_uint4(ra[4*j], ra[4*j+1], ra[4*j+2], ra[4*j+3]);
            *(uint4*)&dB[4*j] = make_uint4(rb[4*j], rb[4*j+1], rb[4*j+2], rb[4*j+3]);
        }
    }
    __syncthreads();

    for (int ch = 0; ch < DIM / 32; ch++) {
        const int cur = ch & 1;
        if (ch + 1 < DIM / 32) {
            const int k0 = (ch + 1) * 32;
#pragma unroll
            for (int j = 0; j < 4; j++) {
                float4 xa = *(const float4*)&X [(size_t)(m0 + srow) * DIM + k0 + scol + 4*j];
                float4 xb = *(const float4*)&Wt[(size_t)(n0 + srow) * DIM + k0 + scol + 4*j];
                ra[4*j+0] = f2tf32(xa.x); ra[4*j+1] = f2tf32(xa.y);
                ra[4*j+2] = f2tf32(xa.z); ra[4*j+3] = f2tf32(xa.w);
                rb[4*j+0] = f2tf32(xb.x); rb[4*j+1] = f2tf32(xb.y);
                rb[4*j+2] = f2tf32(xb.z); rb[4*j+3] = f2tf32(xb.w);
            }
        }
        const uint32_t* smA = sm + cur * BUFSZ;
        const uint32_t* smB = smA + ABUF;
#pragma unroll
        for (int kk = 0; kk < 4; kk++) {
            const int col = kk * 8 + t4;
            uint32_t af[2][4], bf[8][2];
#pragma unroll
            for (int mt = 0; mt < 2; mt++) {
                const int r0 = (warpM * 32 + mt * 16 + g) * SROW;
                af[mt][0] = smA[r0 + col];
                af[mt][1] = smA[r0 + 8 * SROW + col];
                af[mt][2] = smA[r0 + col + 4];
                af[mt][3] = smA[r0 + 8 * SROW + col + 4];
            }
#pragma unroll
            for (int nt = 0; nt < 8; nt++) {
                const int rn = (warpN * 64 + nt * 8 + g) * SROW;
                bf[nt][0] = smB[rn + col];
                bf[nt][1] = smB[rn + col + 4];
            }
#pragma unroll
            for (int mt = 0; mt < 2; mt++)
#pragma unroll
                for (int nt = 0; nt < 8; nt++)
                    mma_tf32(c[mt][nt], af[mt], bf[nt]);
        }
        if (ch + 1 < DIM / 32) {
            uint32_t* dA = sm + (cur ^ 1) * BUFSZ + srow * SROW + scol;
            uint32_t* dB = dA + ABUF;
#pragma unroll
            for (int j = 0; j < 4; j++) {
                *(uint4*)&dA[4*j] = make_uint4(ra[4*j], ra[4*j+1], ra[4*j+2], ra[4*j+3]);
                *(uint4*)&dB[4*j] = make_uint4(rb[4*j], rb[4*j+1], rb[4*j+2], rb[4*j+3]);
            }
        }
        __syncthreads();
    }

#pragma unroll
    for (int mt = 0; mt < 2; mt++) {
#pragma unroll
        for (int nt = 0; nt < 8; nt++) {
            const int row  = m0 + warpM * 32 + mt * 16 + g;
            const int coln = n0 + warpN * 64 + nt * 8 + t4 * 2;
            const float b0 = bias[coln], b1 = bias[coln + 1];
            float v0 = c[mt][nt][0] + b0;
            float v1 = c[mt][nt][1] + b1;
            float v2 = c[mt][nt][2] + b0;
            float v3 = c[mt][nt][3] + b1;
            if (act) {
                v0 = 1.0f / (1.0f + __expf(-v0));
                v1 = 1.0f / (1.0f + __expf(-v1));
                v2 = 1.0f / (1.0f + __expf(-v2));
                v3 = 1.0f / (1.0f + __expf(-v3));
            }
            *(float2*)&C[(size_t)row * DIM + coln]       = make_float2(v0, v1);
            *(float2*)&C[(size_t)(row + 8) * DIM + coln] = make_float2(v2, v3);
        }
    }
}

// ---------------------------------------------------------------------------
// Chunked linear scan (unchanged)
// ---------------------------------------------------------------------------
__global__ __launch_bounds__(512) void scan_chunks()
{
    const int d  = threadIdx.x;
    const int c  = blockIdx.x;
    const int bb = blockIdx.y;
    size_t base = ((size_t)(bb * TT + c * CHUNK)) * DIM + d;
    float A = 1.0f, h = 0.0f;
#pragma unroll 4
    for (int t = 0; t < CHUNK; t++) {
        float av = g_a[base + (size_t)t * DIM];
        float bv = g_b[base + (size_t)t * DIM];
        h = fmaf(av, h, bv);
        A *= av;
    }
    g_cA[(bb * NCH + c) * DIM + d] = A;
    g_cB[(bb * NCH + c) * DIM + d] = h;
}

__global__ __launch_bounds__(512) void scan_carry()
{
    const int d  = threadIdx.x;
    const int bb = blockIdx.x;
    float h = 0.0f;
#pragma unroll
    for (int c = 0; c < NCH; c++) {
        const int idx = (bb * NCH + c) * DIM + d;
        g_pref[idx] = h;
        h = fmaf(g_cA[idx], h, g_cB[idx]);
    }
}

__global__ __launch_bounds__(512) void scan_apply()
{
    const int d  = threadIdx.x;
    const int c  = blockIdx.x;
    const int bb = blockIdx.y;
    size_t base = ((size_t)(bb * TT + c * CHUNK)) * DIM + d;
    float h = g_pref[(bb * NCH + c) * DIM + d];
#pragma unroll 4
    for (int t = 0; t < CHUNK; t++) {
        float av = g_a[base + (size_t)t * DIM];
        float bv = g_b[base + (size_t)t * DIM];
        h = fmaf(av, h, bv);
        g_hg[base + (size_t)t * DIM] = h * g_g[base + (size_t)t * DIM];
    }
}

// ---------------------------------------------------------------------------
// Retention via fp16 mma.sync (windowed, WIN=256):
// out[b,t,h*64+d] += sum_s (q_t.k_s) * 0.9^(t-s) * v_s[d]
// Block = (t-tile 64, head, batch), 8 warps. s-chunks of 64.
// ---------------------------------------------------------------------------
#define SR   36   // u32 stride for Qs/Ks/Ss
#define SRV  38   // u32 stride for Vt

__device__ __forceinline__ uint32_t packh2(float lo, float hi) {
    __half2 h = __floats2half2_rn(lo, hi);
    return *(uint32_t*)&h;
}

__device__ __forceinline__ void mma_f16(
    float c[4], const uint32_t a[4], uint32_t b0, uint32_t b1)
{
    asm volatile(
        "mma.sync.aligned.m16n8k16.row.col.f32.f16.f16.f32 "
        "{%0,%1,%2,%3}, {%4,%5,%6,%7}, {%8,%9}, {%0,%1,%2,%3};"
        : "+f"(c[0]), "+f"(c[1]), "+f"(c[2]), "+f"(c[3])
        : "r"(a[0]), "r"(a[1]), "r"(a[2]), "r"(a[3]), "r"(b0), "r"(b1));
}

__global__ __launch_bounds__(256) void retention_mma(
    const float* __restrict__ q, const float* __restrict__ k,
    const float* __restrict__ v, float* __restrict__ out)
{
    __shared__ uint32_t Qs[64 * SR];
    __shared__ uint32_t Ks[64 * SR];
    __shared__ uint32_t Ss[64 * SR];
    __shared__ uint32_t Vt[64 * SRV];

    const int tid  = threadIdx.x;
    const int lane = tid & 31;
    const int wid  = tid >> 5;
    const int g    = lane >> 2;
    const int t4   = lane & 3;
    const int tb   = (wid & 3) * 16;      // warp t-strip
    const int nb   = (wid >> 2) * 32;     // warp n-strip (s for S, d for O)

    const int t0 = blockIdx.x * TBLK;
    const int hh = blockIdx.y;
    const int bb = blockIdx.z;

    const float* qb = q + (size_t)bb * TT * DIM + hh * DH;
    const float* kb = k + (size_t)bb * TT * DIM + hh * DH;
    const float* vb = v + (size_t)bb * TT * DIM + hh * DH;

    // tile staging mapping (Q, K): row 0..63, 16 floats along d
    const int row = tid >> 2;
    const int dg  = (tid & 3) * 16;
    // V staging mapping: 4 d-cols x 4 s-rows per thread
    const int vd0 = (tid & 15) * 4;
    const int vs0 = (tid >> 4) * 4;

    // ---- load Q tile as fp16 ----
    {
        const float4* qrow = (const float4*)&qb[(size_t)(t0 + row) * DIM + dg];
        uint32_t tmp[8];
#pragma unroll
        for (int i = 0; i < 4; i++) {
            float4 x = qrow[i];
            tmp[2*i]   = packh2(x.x, x.y);
            tmp[2*i+1] = packh2(x.z, x.w);
        }
        *(uint4*)&Qs[row * SR + (tid & 3) * 8]     = make_uint4(tmp[0], tmp[1], tmp[2], tmp[3]);
        *(uint4*)&Qs[row * SR + (tid & 3) * 8 + 4] = make_uint4(tmp[4], tmp[5], tmp[6], tmp[7]);
    }
    __syncthreads();

    // ---- cache Q A-fragments across chunks ----
    uint32_t afq[4][4];
#pragma unroll
    for (int kk = 0; kk < 4; kk++) {
        afq[kk][0] = Qs[(tb + g)     * SR + kk * 8 + t4];
        afq[kk][1] = Qs[(tb + g + 8) * SR + kk * 8 + t4];
        afq[kk][2] = Qs[(tb + g)     * SR + kk * 8 + t4 + 4];
        afq[kk][3] = Qs[(tb + g + 8) * SR + kk * 8 + t4 + 4];
    }

    // ---- per-thread D^{-s} factors (chunk-independent) ----
    float dsv[4][2];
    dsv[0][0] = exp2f(-L2DECAY * (float)(nb + 2 * t4));
    dsv[0][1] = dsv[0][0] * DINV;
#pragma unroll
    for (int nf = 1; nf < 4; nf++) {
        dsv[nf][0] = dsv[nf-1][0] * DM8INV;
        dsv[nf][1] = dsv[nf-1][1] * DM8INV;
    }

    float co[4][4];
#pragma unroll
    for (int nf = 0; nf < 4; nf++)
#pragma unroll
        for (int r = 0; r < 4; r++) co[nf][r] = 0.0f;

    const int sBeg = (t0 >= WIN) ? (t0 - WIN) : 0;

    for (int s0 = sBeg; s0 <= t0; s0 += SCH) {
        // prefetch K, V chunk to registers
        float4 kx[4], vx[4];
        {
            const float4* krow = (const float4*)&kb[(size_t)(s0 + row) * DIM + dg];
#pragma unroll
            for (int i = 0; i < 4; i++) kx[i] = krow[i];
#pragma unroll
            for (int i = 0; i < 4; i++)
                vx[i] = *(const float4*)&vb[(size_t)(s0 + vs0 + i) * DIM + vd0];
        }
        __syncthreads();   // previous chunk's O-mma done reading Ks/Vt/Ss

        // stage K (row-major halves)
        {
            uint32_t tmp[8];
#pragma unroll
            for (int i = 0; i < 4; i++) {
                tmp[2*i]   = packh2(kx[i].x, kx[i].y);
                tmp[2*i+1] = packh2(kx[i].z, kx[i].w);
            }
            *(uint4*)&Ks[row * SR + (tid & 3) * 8]     = make_uint4(tmp[0], tmp[1], tmp[2], tmp[3]);
            *(uint4*)&Ks[row * SR + (tid & 3) * 8 + 4] = make_uint4(tmp[4], tmp[5], tmp[6], tmp[7]);
        }
        // stage V transposed: Vt[d][s]
        {
            const float vr[4][4] = {
                {vx[0].x, vx[0].y, vx[0].z, vx[0].w},
                {vx[1].x, vx[1].y, vx[1].z, vx[1].w},
                {vx[2].x, vx[2].y, vx[2].z, vx[2].w},
                {vx[3].x, vx[3].y, vx[3].z, vx[3].w}};
#pragma unroll
            for (int j = 0; j < 4; j++) {
                Vt[(vd0 + j) * SRV + (vs0 >> 1)]     = packh2(vr[0][j], vr[1][j]);
                Vt[(vd0 + j) * SRV + (vs0 >> 1) + 1] = packh2(vr[2][j], vr[3][j]);
            }
        }
        __syncthreads();

        // ---- S = Q . K^T  (warp strip: rows tb..tb+16, cols nb..nb+32) ----
        float cs[4][4];
#pragma unroll
        for (int nf = 0; nf < 4; nf++)
#pragma unroll
            for (int r = 0; r < 4; r++) cs[nf][r] = 0.0f;
#pragma unroll
        for (int kk = 0; kk < 4; kk++) {
#pragma unroll
            for (int nf = 0; nf < 4; nf++) {
                const int rn = (nb + nf * 8 + g) * SR + kk * 8 + t4;
                mma_f16(cs[nf], afq[kk], Ks[rn], Ks[rn + 4]);
            }
        }

        // ---- decay + mask, store S as fp16 ----
        const int off = t0 - s0;
        const float Dt0 = exp2f((float)(tb + g + off) * L2DECAY);
        const float Dt1 = Dt0 * D8;
#pragma unroll
        for (int nf = 0; nf < 4; nf++) {
            const int scol = nb + nf * 8 + 2 * t4;
            const int d0 = tb + g + off - scol;
            float w00 = (d0     >= 0) ? Dt0 * dsv[nf][0] : 0.0f;
            float w01 = (d0 - 1 >= 0) ? Dt0 * dsv[nf][1] : 0.0f;
            float w10 = (d0 + 8 >= 0) ? Dt1 * dsv[nf][0] : 0.0f;
            float w11 = (d0 + 7 >= 0) ? Dt1 * dsv[nf][1] : 0.0f;
            Ss[(tb + g)     * SR + (nb >> 1) + nf * 4 + t4] = packh2(cs[nf][0] * w00, cs[nf][1] * w01);
            Ss[(tb + g + 8) * SR + (nb >> 1) + nf * 4 + t4] = packh2(cs[nf][2] * w10, cs[nf][3] * w11);
        }
        __syncthreads();

        // ---- O += S . V  (warp strip: rows tb..tb+16, d-cols nb..nb+32) ----
#pragma unroll
        for (int kk = 0; kk < 4; kk++) {
            uint32_t as[4];
            as[0] = Ss[(tb + g)     * SR + kk * 8 + t4];
            as[1] = Ss[(tb + g + 8) * SR + kk * 8 + t4];
            as[2] = Ss[(tb + g)     * SR + kk * 8 + t4 + 4];
            as[3] = Ss[(tb + g + 8) * SR + kk * 8 + t4 + 4];
#pragma unroll
            for (int nf = 0; nf < 4; nf++) {
                const int rn = (nb + nf * 8 + g) * SRV + kk * 8 + t4;
                mma_f16(co[nf], as, Vt[rn], Vt[rn + 4]);
            }
        }
    }

    // ---- epilogue: accumulate into out ----
#pragma unroll
    for (int nf = 0; nf < 4; nf++) {
        const int col = hh * DH + nb + nf * 8 + 2 * t4;
        float2* p0 = (float2*)&out[((size_t)bb * TT + t0 + tb + g)     * DIM + col];
        float2* p1 = (float2*)&out[((size_t)bb * TT + t0 + tb + g + 8) * DIM + col];
        float2 o0 = *p0, o1 = *p1;
        o0.x += co[nf][0]; o0.y += co[nf][1];
        o1.x += co[nf][2]; o1.y += co[nf][3];
        *p0 = o0; *p1 = o1;
    }
}

// ---------------------------------------------------------------------------
extern "C" void kernel_launch(void* const* d_in, const int* in_sizes, int n_in,
                              void* d_out, int out_size)
{
    const float* q  = (const float*)d_in[0];
    const float* k  = (const float*)d_in[1];
    const float* v  = (const float*)d_in[2];
    const float* Wa = (const float*)d_in[3];
    const float* ba = (const float*)d_in[4];
    const float* Wb = (const float*)d_in[5];
    const float* bb = (const float*)d_in[6];
    const float* Wg = (const float*)d_in[7];
    const float* bg = (const float*)d_in[8];
    const float* Wo = (const float*)d_in[9];
    const float* bo = (const float*)d_in[10];
    float* out = (float*)d_out;

    float *pa, *pb, *pg, *phg, *pwt;
    cudaGetSymbolAddress((void**)&pa,  g_a);
    cudaGetSymbolAddress((void**)&pb,  g_b);
    cudaGetSymbolAddress((void**)&pg,  g_g);
    cudaGetSymbolAddress((void**)&phg, g_hg);
    cudaGetSymbolAddress((void**)&pwt, g_Wt);

    cudaFuncSetAttribute(gemm_mma, cudaFuncAttributeMaxDynamicSharedMemorySize,
                         GSMEM_BYTES);

    transposeW4<<<dim3(DIM / 32, DIM / 32, 4), dim3(32, 8)>>>(Wa, Wb, Wg, Wo, pwt);

    dim3 gg(DIM / 128, MROWS / 128);   // 4 x 64
    gemm_mma<<<gg, 256, GSMEM_BYTES>>>(q, pwt + 0 * DIM * DIM, ba, pa, 1);
    gemm_mma<<<gg, 256, GSMEM_BYTES>>>(q, pwt + 1 * DIM * DIM, bb, pb, 0);
    gemm_mma<<<gg, 256, GSMEM_BYTES>>>(q, pwt + 2 * DIM * DIM, bg, pg, 1);

    scan_chunks<<<dim3(NCH, BB), 512>>>();
    scan_carry<<<BB, 512>>>();
    scan_apply<<<dim3(NCH, BB), 512>>>();

    gemm_mma<<<gg, 256, GSMEM_BYTES>>>(phg, pwt + 3 * DIM * DIM, bo, out, 0);

    retention_mma<<<dim3(TT / TBLK, NH, BB), 256>>>(q, k, v, out);
}

// round 5
// speedup vs baseline: 3.6544x; 1.4637x over previous
#include <cuda_runtime.h>
#include <cuda_fp16.h>
#include <math.h>
#include <stdint.h>

// Problem constants
#define BB    4
#define TT    2048
#define DIM   512
#define NH    8
#define DH    64
#define MROWS (BB*TT)      // 8192
#define CHUNK 64
#define NCH   (TT/CHUNK)   // 32
#define WIN   256
#define TBLK  64           // retention t-tile
#define SCH   64           // retention s-chunk

#define L2DECAY (-0.15200309344504997f)   // log2(0.9)
#define D8      (0.43046721f)             // 0.9^8
#define DINV    (1.1111111111111112f)     // 0.9^-1
#define DM8INV  (2.3230573202841774f)     // 0.9^-8

// Scratch (allocation-free rule: __device__ globals)
__device__ float  g_a [MROWS*DIM];
__device__ float  g_b [MROWS*DIM];
__device__ float  g_g [MROWS*DIM];
__device__ __half g_hgh[MROWS*DIM];
__device__ __half g_qh [MROWS*DIM];
__device__ float  g_cA  [BB*NCH*DIM];
__device__ float  g_cB  [BB*NCH*DIM];
__device__ float  g_pref[BB*NCH*DIM];
__device__ __half g_Wth[4][DIM*DIM];   // transposed fp16 weights [n][k]

__device__ __forceinline__ uint32_t smem_u32(const void* p) {
    uint32_t a;
    asm("{ .reg .u64 t; cvta.to.shared.u64 t, %1; cvt.u32.u64 %0, t; }"
        : "=r"(a) : "l"(p));
    return a;
}

// ---------------------------------------------------------------------------
// Fused weight transpose + fp16 convert: Wth[z][n][k] = (half)W_z[k][n]
// ---------------------------------------------------------------------------
__global__ __launch_bounds__(256) void transposeW4h(
    const float* __restrict__ W0, const float* __restrict__ W1,
    const float* __restrict__ W2, const float* __restrict__ W3,
    __half* __restrict__ Wt)
{
    __shared__ float t[32][33];
    const float* W = (blockIdx.z == 0) ? W0 : (blockIdx.z == 1) ? W1
                   : (blockIdx.z == 2) ? W2 : W3;
    __half* Wtz = Wt + (size_t)blockIdx.z * DIM * DIM;
    const int tx = threadIdx.x, ty = threadIdx.y;   // 32 x 8
    const int k0 = blockIdx.x * 32, n0 = blockIdx.y * 32;
#pragma unroll
    for (int j = 0; j < 32; j += 8)
        t[ty + j][tx] = W[(size_t)(k0 + ty + j) * DIM + n0 + tx];
    __syncthreads();
#pragma unroll
    for (int j = 0; j < 32; j += 8)
        Wtz[(size_t)(n0 + ty + j) * DIM + k0 + tx] = __float2half(t[tx][ty + j]);
}

// ---------------------------------------------------------------------------
// f32 -> fp16 bulk convert (8 elems per thread)
// ---------------------------------------------------------------------------
__global__ __launch_bounds__(256) void f2h_bulk(
    const float* __restrict__ x, __half* __restrict__ y)
{
    const size_t i = ((size_t)blockIdx.x * 256 + threadIdx.x) * 8;
    float4 v0 = *(const float4*)&x[i];
    float4 v1 = *(const float4*)&x[i + 4];
    __half2 h[4];
    h[0] = __floats2half2_rn(v0.x, v0.y);
    h[1] = __floats2half2_rn(v0.z, v0.w);
    h[2] = __floats2half2_rn(v1.x, v1.y);
    h[3] = __floats2half2_rn(v1.z, v1.w);
    *(uint4*)&y[i] = *(uint4*)h;
}

// ---------------------------------------------------------------------------
// fp16 mma.sync GEMM with ldmatrix: C[8192x512] = act(X @ Wt^T + bias)
// X fp16 [M,K], Wt fp16 [N,K]. CTA 128x128, 8 warps (32x64 each), BK=32.
// smem rows padded to 40 halves (80B) -> conflict-free ldmatrix.
// ---------------------------------------------------------------------------
#define HSR   40
#define HABUF (128 * HSR)    // halves per operand tile

__device__ __forceinline__ void ldsm_x4(uint32_t r[4], uint32_t addr) {
    asm volatile("ldmatrix.sync.aligned.m8n8.x4.shared.b16 {%0,%1,%2,%3}, [%4];"
                 : "=r"(r[0]), "=r"(r[1]), "=r"(r[2]), "=r"(r[3]) : "r"(addr));
}

__device__ __forceinline__ void mma_f16(
    float c[4], const uint32_t a[4], uint32_t b0, uint32_t b1)
{
    asm volatile(
        "mma.sync.aligned.m16n8k16.row.col.f32.f16.f16.f32 "
        "{%0,%1,%2,%3}, {%4,%5,%6,%7}, {%8,%9}, {%0,%1,%2,%3};"
        : "+f"(c[0]), "+f"(c[1]), "+f"(c[2]), "+f"(c[3])
        : "r"(a[0]), "r"(a[1]), "r"(a[2]), "r"(a[3]), "r"(b0), "r"(b1));
}

__global__ __launch_bounds__(256) void gemm_h(
    const __half* __restrict__ X, const __half* __restrict__ Wt,
    const float* __restrict__ bias, float* __restrict__ C, int act)
{
    __shared__ __half sm[2][2 * HABUF];
    const int tid   = threadIdx.x;
    const int lane  = tid & 31;
    const int wid   = tid >> 5;
    const int g     = lane >> 2;
    const int t4    = lane & 3;
    const int warpM = wid & 3;
    const int warpN = wid >> 2;
    const int m0 = blockIdx.y * 128;
    const int n0 = blockIdx.x * 128;

    // staging: thread -> row 0..127, 16 halves
    const int srow = tid >> 1;
    const int scol = (tid & 1) * 16;
    // ldmatrix lane addressing
    const int lrow = lane & 15;
    const int lcol = (lane >> 4) * 8;

    float c[2][8][4];
#pragma unroll
    for (int mt = 0; mt < 2; mt++)
#pragma unroll
        for (int nt = 0; nt < 8; nt++)
#pragma unroll
            for (int r = 0; r < 4; r++) c[mt][nt][r] = 0.0f;

    uint4 ra[2], rb[2];
    ra[0] = *(const uint4*)&X [(size_t)(m0 + srow) * DIM + scol];
    ra[1] = *(const uint4*)&X [(size_t)(m0 + srow) * DIM + scol + 8];
    rb[0] = *(const uint4*)&Wt[(size_t)(n0 + srow) * DIM + scol];
    rb[1] = *(const uint4*)&Wt[(size_t)(n0 + srow) * DIM + scol + 8];
    {
        __half* dA = &sm[0][srow * HSR + scol];
        *(uint4*)dA = ra[0];
        *(uint4*)(dA + 8) = ra[1];
        *(uint4*)(dA + HABUF) = rb[0];
        *(uint4*)(dA + HABUF + 8) = rb[1];
    }
    __syncthreads();

    for (int ch = 0; ch < DIM / 32; ch++) {
        const int cur = ch & 1;
        if (ch + 1 < DIM / 32) {
            const int k0 = (ch + 1) * 32;
            ra[0] = *(const uint4*)&X [(size_t)(m0 + srow) * DIM + k0 + scol];
            ra[1] = *(const uint4*)&X [(size_t)(m0 + srow) * DIM + k0 + scol + 8];
            rb[0] = *(const uint4*)&Wt[(size_t)(n0 + srow) * DIM + k0 + scol];
            rb[1] = *(const uint4*)&Wt[(size_t)(n0 + srow) * DIM + k0 + scol + 8];
        }

        const uint32_t baseA = smem_u32(&sm[cur][0]);
        const uint32_t baseB = baseA + HABUF * 2;
#pragma unroll
        for (int ks = 0; ks < 2; ks++) {
            const int kc = ks * 16 + lcol;
            uint32_t af[2][4];
#pragma unroll
            for (int mt = 0; mt < 2; mt++)
                ldsm_x4(af[mt], baseA + ((warpM * 32 + mt * 16 + lrow) * HSR + kc) * 2);
#pragma unroll
            for (int ng = 0; ng < 4; ng++) {
                uint32_t bq[4];
                ldsm_x4(bq, baseB + ((warpN * 64 + ng * 16 + lrow) * HSR + kc) * 2);
#pragma unroll
                for (int mt = 0; mt < 2; mt++) {
                    mma_f16(c[mt][ng * 2],     af[mt], bq[0], bq[2]);
                    mma_f16(c[mt][ng * 2 + 1], af[mt], bq[1], bq[3]);
                }
            }
        }

        if (ch + 1 < DIM / 32) {
            __half* dA = &sm[cur ^ 1][srow * HSR + scol];
            *(uint4*)dA = ra[0];
            *(uint4*)(dA + 8) = ra[1];
            *(uint4*)(dA + HABUF) = rb[0];
            *(uint4*)(dA + HABUF + 8) = rb[1];
        }
        __syncthreads();
    }

    // epilogue
#pragma unroll
    for (int mt = 0; mt < 2; mt++) {
#pragma unroll
        for (int nt = 0; nt < 8; nt++) {
            const int row  = m0 + warpM * 32 + mt * 16 + g;
            const int coln = n0 + warpN * 64 + nt * 8 + t4 * 2;
            const float b0 = bias[coln], b1 = bias[coln + 1];
            float v0 = c[mt][nt][0] + b0;
            float v1 = c[mt][nt][1] + b1;
            float v2 = c[mt][nt][2] + b0;
            float v3 = c[mt][nt][3] + b1;
            if (act) {
                v0 = 1.0f / (1.0f + __expf(-v0));
                v1 = 1.0f / (1.0f + __expf(-v1));
                v2 = 1.0f / (1.0f + __expf(-v2));
                v3 = 1.0f / (1.0f + __expf(-v3));
            }
            *(float2*)&C[(size_t)row * DIM + coln]       = make_float2(v0, v1);
            *(float2*)&C[(size_t)(row + 8) * DIM + coln] = make_float2(v2, v3);
        }
    }
}

// ---------------------------------------------------------------------------
// Chunked linear scan
// ---------------------------------------------------------------------------
__global__ __launch_bounds__(512) void scan_chunks()
{
    const int d  = threadIdx.x;
    const int c  = blockIdx.x;
    const int bb = blockIdx.y;
    size_t base = ((size_t)(bb * TT + c * CHUNK)) * DIM + d;
    float A = 1.0f, h = 0.0f;
#pragma unroll 4
    for (int t = 0; t < CHUNK; t++) {
        float av = g_a[base + (size_t)t * DIM];
        float bv = g_b[base + (size_t)t * DIM];
        h = fmaf(av, h, bv);
        A *= av;
    }
    g_cA[(bb * NCH + c) * DIM + d] = A;
    g_cB[(bb * NCH + c) * DIM + d] = h;
}

__global__ __launch_bounds__(512) void scan_carry()
{
    const int d  = threadIdx.x;
    const int bb = blockIdx.x;
    float h = 0.0f;
#pragma unroll
    for (int c = 0; c < NCH; c++) {
        const int idx = (bb * NCH + c) * DIM + d;
        g_pref[idx] = h;
        h = fmaf(g_cA[idx], h, g_cB[idx]);
    }
}

__global__ __launch_bounds__(512) void scan_apply()
{
    const int d  = threadIdx.x;
    const int c  = blockIdx.x;
    const int bb = blockIdx.y;
    size_t base = ((size_t)(bb * TT + c * CHUNK)) * DIM + d;
    float h = g_pref[(bb * NCH + c) * DIM + d];
#pragma unroll 4
    for (int t = 0; t < CHUNK; t++) {
        float av = g_a[base + (size_t)t * DIM];
        float bv = g_b[base + (size_t)t * DIM];
        h = fmaf(av, h, bv);
        g_hgh[base + (size_t)t * DIM] = __float2half(h * g_g[base + (size_t)t * DIM]);
    }
}

// ---------------------------------------------------------------------------
// Retention via fp16 mma.sync (windowed, WIN=256)
// ---------------------------------------------------------------------------
#define SR   36   // u32 stride for Qs/Ks/Ss
#define SRV  38   // u32 stride for Vt

__device__ __forceinline__ uint32_t packh2(float lo, float hi) {
    __half2 h = __floats2half2_rn(lo, hi);
    return *(uint32_t*)&h;
}

__global__ __launch_bounds__(256) void retention_mma(
    const float* __restrict__ q, const float* __restrict__ k,
    const float* __restrict__ v, float* __restrict__ out)
{
    __shared__ uint32_t Qs[64 * SR];
    __shared__ uint32_t Ks[64 * SR];
    __shared__ uint32_t Ss[64 * SR];
    __shared__ uint32_t Vt[64 * SRV];

    const int tid  = threadIdx.x;
    const int lane = tid & 31;
    const int wid  = tid >> 5;
    const int g    = lane >> 2;
    const int t4   = lane & 3;
    const int tb   = (wid & 3) * 16;
    const int nb   = (wid >> 2) * 32;

    const int t0 = blockIdx.x * TBLK;
    const int hh = blockIdx.y;
    const int bb = blockIdx.z;

    const float* qb = q + (size_t)bb * TT * DIM + hh * DH;
    const float* kb = k + (size_t)bb * TT * DIM + hh * DH;
    const float* vb = v + (size_t)bb * TT * DIM + hh * DH;

    const int row = tid >> 2;
    const int dg  = (tid & 3) * 16;
    const int vd0 = (tid & 15) * 4;
    const int vs0 = (tid >> 4) * 4;

    {
        const float4* qrow = (const float4*)&qb[(size_t)(t0 + row) * DIM + dg];
        uint32_t tmp[8];
#pragma unroll
        for (int i = 0; i < 4; i++) {
            float4 x = qrow[i];
            tmp[2*i]   = packh2(x.x, x.y);
            tmp[2*i+1] = packh2(x.z, x.w);
        }
        *(uint4*)&Qs[row * SR + (tid & 3) * 8]     = make_uint4(tmp[0], tmp[1], tmp[2], tmp[3]);
        *(uint4*)&Qs[row * SR + (tid & 3) * 8 + 4] = make_uint4(tmp[4], tmp[5], tmp[6], tmp[7]);
    }
    __syncthreads();

    uint32_t afq[4][4];
#pragma unroll
    for (int kk = 0; kk < 4; kk++) {
        afq[kk][0] = Qs[(tb + g)     * SR + kk * 8 + t4];
        afq[kk][1] = Qs[(tb + g + 8) * SR + kk * 8 + t4];
        afq[kk][2] = Qs[(tb + g)     * SR + kk * 8 + t4 + 4];
        afq[kk][3] = Qs[(tb + g + 8) * SR + kk * 8 + t4 + 4];
    }

    float dsv[4][2];
    dsv[0][0] = exp2f(-L2DECAY * (float)(nb + 2 * t4));
    dsv[0][1] = dsv[0][0] * DINV;
#pragma unroll
    for (int nf = 1; nf < 4; nf++) {
        dsv[nf][0] = dsv[nf-1][0] * DM8INV;
        dsv[nf][1] = dsv[nf-1][1] * DM8INV;
    }

    float co[4][4];
#pragma unroll
    for (int nf = 0; nf < 4; nf++)
#pragma unroll
        for (int r = 0; r < 4; r++) co[nf][r] = 0.0f;

    const int sBeg = (t0 >= WIN) ? (t0 - WIN) : 0;

    for (int s0 = sBeg; s0 <= t0; s0 += SCH) {
        float4 kx[4], vx[4];
        {
            const float4* krow = (const float4*)&kb[(size_t)(s0 + row) * DIM + dg];
#pragma unroll
            for (int i = 0; i < 4; i++) kx[i] = krow[i];
#pragma unroll
            for (int i = 0; i < 4; i++)
                vx[i] = *(const float4*)&vb[(size_t)(s0 + vs0 + i) * DIM + vd0];
        }
        __syncthreads();

        {
            uint32_t tmp[8];
#pragma unroll
            for (int i = 0; i < 4; i++) {
                tmp[2*i]   = packh2(kx[i].x, kx[i].y);
                tmp[2*i+1] = packh2(kx[i].z, kx[i].w);
            }
            *(uint4*)&Ks[row * SR + (tid & 3) * 8]     = make_uint4(tmp[0], tmp[1], tmp[2], tmp[3]);
            *(uint4*)&Ks[row * SR + (tid & 3) * 8 + 4] = make_uint4(tmp[4], tmp[5], tmp[6], tmp[7]);
        }
        {
            const float vr[4][4] = {
                {vx[0].x, vx[0].y, vx[0].z, vx[0].w},
                {vx[1].x, vx[1].y, vx[1].z, vx[1].w},
                {vx[2].x, vx[2].y, vx[2].z, vx[2].w},
                {vx[3].x, vx[3].y, vx[3].z, vx[3].w}};
#pragma unroll
            for (int j = 0; j < 4; j++) {
                Vt[(vd0 + j) * SRV + (vs0 >> 1)]     = packh2(vr[0][j], vr[1][j]);
                Vt[(vd0 + j) * SRV + (vs0 >> 1) + 1] = packh2(vr[2][j], vr[3][j]);
            }
        }
        __syncthreads();

        float cs[4][4];
#pragma unroll
        for (int nf = 0; nf < 4; nf++)
#pragma unroll
            for (int r = 0; r < 4; r++) cs[nf][r] = 0.0f;
#pragma unroll
        for (int kk = 0; kk < 4; kk++) {
#pragma unroll
            for (int nf = 0; nf < 4; nf++) {
                const int rn = (nb + nf * 8 + g) * SR + kk * 8 + t4;
                mma_f16(cs[nf], afq[kk], Ks[rn], Ks[rn + 4]);
            }
        }

        const int off = t0 - s0;
        const float Dt0 = exp2f((float)(tb + g + off) * L2DECAY);
        const float Dt1 = Dt0 * D8;
#pragma unroll
        for (int nf = 0; nf < 4; nf++) {
            const int scol = nb + nf * 8 + 2 * t4;
            const int d0 = tb + g + off - scol;
            float w00 = (d0     >= 0) ? Dt0 * dsv[nf][0] : 0.0f;
            float w01 = (d0 - 1 >= 0) ? Dt0 * dsv[nf][1] : 0.0f;
            float w10 = (d0 + 8 >= 0) ? Dt1 * dsv[nf][0] : 0.0f;
            float w11 = (d0 + 7 >= 0) ? Dt1 * dsv[nf][1] : 0.0f;
            Ss[(tb + g)     * SR + (nb >> 1) + nf * 4 + t4] = packh2(cs[nf][0] * w00, cs[nf][1] * w01);
            Ss[(tb + g + 8) * SR + (nb >> 1) + nf * 4 + t4] = packh2(cs[nf][2] * w10, cs[nf][3] * w11);
        }
        __syncthreads();

#pragma unroll
        for (int kk = 0; kk < 4; kk++) {
            uint32_t as[4];
            as[0] = Ss[(tb + g)     * SR + kk * 8 + t4];
            as[1] = Ss[(tb + g + 8) * SR + kk * 8 + t4];
            as[2] = Ss[(tb + g)     * SR + kk * 8 + t4 + 4];
            as[3] = Ss[(tb + g + 8) * SR + kk * 8 + t4 + 4];
#pragma unroll
            for (int nf = 0; nf < 4; nf++) {
                const int rn = (nb + nf * 8 + g) * SRV + kk * 8 + t4;
                mma_f16(co[nf], as, Vt[rn], Vt[rn + 4]);
            }
        }
    }

#pragma unroll
    for (int nf = 0; nf < 4; nf++) {
        const int col = hh * DH + nb + nf * 8 + 2 * t4;
        float2* p0 = (float2*)&out[((size_t)bb * TT + t0 + tb + g)     * DIM + col];
        float2* p1 = (float2*)&out[((size_t)bb * TT + t0 + tb + g + 8) * DIM + col];
        float2 o0 = *p0, o1 = *p1;
        o0.x += co[nf][0]; o0.y += co[nf][1];
        o1.x += co[nf][2]; o1.y += co[nf][3];
        *p0 = o0; *p1 = o1;
    }
}

// ---------------------------------------------------------------------------
extern "C" void kernel_launch(void* const* d_in, const int* in_sizes, int n_in,
                              void* d_out, int out_size)
{
    const float* q  = (const float*)d_in[0];
    const float* k  = (const float*)d_in[1];
    const float* v  = (const float*)d_in[2];
    const float* Wa = (const float*)d_in[3];
    const float* ba = (const float*)d_in[4];
    const float* Wb = (const float*)d_in[5];
    const float* bb = (const float*)d_in[6];
    const float* Wg = (const float*)d_in[7];
    const float* bg = (const float*)d_in[8];
    const float* Wo = (const float*)d_in[9];
    const float* bo = (const float*)d_in[10];
    float* out = (float*)d_out;

    float *pa, *pb, *pg;
    __half *phgh, *pqh, *pwth;
    cudaGetSymbolAddress((void**)&pa,   g_a);
    cudaGetSymbolAddress((void**)&pb,   g_b);
    cudaGetSymbolAddress((void**)&pg,   g_g);
    cudaGetSymbolAddress((void**)&phgh, g_hgh);
    cudaGetSymbolAddress((void**)&pqh,  g_qh);
    cudaGetSymbolAddress((void**)&pwth, g_Wth);

    transposeW4h<<<dim3(DIM / 32, DIM / 32, 4), dim3(32, 8)>>>(Wa, Wb, Wg, Wo, pwth);
    f2h_bulk<<<(MROWS * DIM) / (256 * 8), 256>>>(q, pqh);

    dim3 gg(DIM / 128, MROWS / 128);   // 4 x 64
    gemm_h<<<gg, 256>>>(pqh, pwth + 0 * DIM * DIM, ba, pa, 1);
    gemm_h<<<gg, 256>>>(pqh, pwth + 1 * DIM * DIM, bb, pb, 0);
    gemm_h<<<gg, 256>>>(pqh, pwth + 2 * DIM * DIM, bg, pg, 1);

    scan_chunks<<<dim3(NCH, BB), 512>>>();
    scan_carry<<<BB, 512>>>();
    scan_apply<<<dim3(NCH, BB), 512>>>();

    gemm_h<<<gg, 256>>>(phgh, pwth + 3 * DIM * DIM, bo, out, 0);

    retention_mma<<<dim3(TT / TBLK, NH, BB), 256>>>(q, k, v, out);
}

// round 6
// speedup vs baseline: 3.9189x; 1.0724x over previous
#include <cuda_runtime.h>
#include <cuda_fp16.h>
#include <math.h>
#include <stdint.h>

// Problem constants
#define BB    4
#define TT    2048
#define DIM   512
#define NH    8
#define DH    64
#define MROWS (BB*TT)      // 8192
#define CHUNK 64
#define NCH   (TT/CHUNK)   // 32
#define WIN   256
#define TBLK  64
#define SCH   64

#define L2DECAY (-0.15200309344504997f)   // log2(0.9)
#define D8      (0.43046721f)             // 0.9^8
#define DINV    (1.1111111111111112f)     // 0.9^-1
#define DM8INV  (2.3230573202841774f)     // 0.9^-8

// Scratch (allocation-free rule: __device__ globals)
__device__ __half g_ah [MROWS*DIM];
__device__ __half g_bh [MROWS*DIM];
__device__ __half g_gh [MROWS*DIM];
__device__ __half g_hgh[MROWS*DIM];
__device__ __half g_qh [MROWS*DIM];
__device__ float  g_cA  [BB*NCH*DIM];
__device__ float  g_cB  [BB*NCH*DIM];
__device__ float  g_pref[BB*NCH*DIM];
__device__ __half g_Wth[4][DIM*DIM];   // transposed fp16 weights [n][k]

__device__ __forceinline__ uint32_t smem_u32(const void* p) {
    uint32_t a;
    asm("{ .reg .u64 t; cvta.to.shared.u64 t, %1; cvt.u32.u64 %0, t; }"
        : "=r"(a) : "l"(p));
    return a;
}

// ---------------------------------------------------------------------------
// Fused weight transpose + fp16 convert
// ---------------------------------------------------------------------------
__global__ __launch_bounds__(256) void transposeW4h(
    const float* __restrict__ W0, const float* __restrict__ W1,
    const float* __restrict__ W2, const float* __restrict__ W3,
    __half* __restrict__ Wt)
{
    __shared__ float t[32][33];
    const float* W = (blockIdx.z == 0) ? W0 : (blockIdx.z == 1) ? W1
                   : (blockIdx.z == 2) ? W2 : W3;
    __half* Wtz = Wt + (size_t)blockIdx.z * DIM * DIM;
    const int tx = threadIdx.x, ty = threadIdx.y;
    const int k0 = blockIdx.x * 32, n0 = blockIdx.y * 32;
#pragma unroll
    for (int j = 0; j < 32; j += 8)
        t[ty + j][tx] = W[(size_t)(k0 + ty + j) * DIM + n0 + tx];
    __syncthreads();
#pragma unroll
    for (int j = 0; j < 32; j += 8)
        Wtz[(size_t)(n0 + ty + j) * DIM + k0 + tx] = __float2half(t[tx][ty + j]);
}

// ---------------------------------------------------------------------------
// f32 -> fp16 bulk convert
// ---------------------------------------------------------------------------
__global__ __launch_bounds__(256) void f2h_bulk(
    const float* __restrict__ x, __half* __restrict__ y)
{
    const size_t i = ((size_t)blockIdx.x * 256 + threadIdx.x) * 8;
    float4 v0 = *(const float4*)&x[i];
    float4 v1 = *(const float4*)&x[i + 4];
    __half2 h[4];
    h[0] = __floats2half2_rn(v0.x, v0.y);
    h[1] = __floats2half2_rn(v0.z, v0.w);
    h[2] = __floats2half2_rn(v1.x, v1.y);
    h[3] = __floats2half2_rn(v1.z, v1.w);
    *(uint4*)&y[i] = *(uint4*)h;
}

// ---------------------------------------------------------------------------
// GEMM mainloop: cp.async 3-stage pipeline + ldmatrix + m16n8k16 fp16 MMA
// CTA 128x128, BK=32, 8 warps (32x64 warp tile).
// ---------------------------------------------------------------------------
#define HSR    40                       // halves per smem row (80B)
#define HABUF  (128 * HSR)              // halves per operand tile
#define STGB   (2 * HABUF * 2)          // bytes per stage (A+B) = 20480
#define NSTG   3
#define PIPE_SMEM (NSTG * STGB)         // 61440 bytes

__device__ __forceinline__ void cp16(uint32_t dst, const void* src) {
    asm volatile("cp.async.ca.shared.global [%0], [%1], 16;"
                 :: "r"(dst), "l"(src));
}
#define CP_COMMIT() asm volatile("cp.async.commit_group;")
#define CP_WAIT1()  asm volatile("cp.async.wait_group 1;")

__device__ __forceinline__ void ldsm_x4(uint32_t r[4], uint32_t addr) {
    asm volatile("ldmatrix.sync.aligned.m8n8.x4.shared.b16 {%0,%1,%2,%3}, [%4];"
                 : "=r"(r[0]), "=r"(r[1]), "=r"(r[2]), "=r"(r[3]) : "r"(addr));
}

__device__ __forceinline__ void mma_f16(
    float c[4], const uint32_t a[4], uint32_t b0, uint32_t b1)
{
    asm volatile(
        "mma.sync.aligned.m16n8k16.row.col.f32.f16.f16.f32 "
        "{%0,%1,%2,%3}, {%4,%5,%6,%7}, {%8,%9}, {%0,%1,%2,%3};"
        : "+f"(c[0]), "+f"(c[1]), "+f"(c[2]), "+f"(c[3])
        : "r"(a[0]), "r"(a[1]), "r"(a[2]), "r"(a[3]), "r"(b0), "r"(b1));
}

__device__ __forceinline__ void gemm_mainloop(
    const __half* __restrict__ X, const __half* __restrict__ Wt,
    int m0, int n0, __half* sm, float c[2][8][4])
{
    const int tid  = threadIdx.x;
    const int lane = tid & 31;
    const int wid  = tid >> 5;
    const int warpM = wid & 3;
    const int warpN = wid >> 2;
    const int lrow = lane & 15;
    const int lcol = (lane >> 4) * 8;

    const uint32_t smbase = smem_u32(sm);
    // cp.async mapping: 2 threads per row; each thread 2x16B per operand
    const int arow = tid >> 1;
    const int ab   = (tid & 1) * 32;    // byte offset within 64B row chunk
    const __half* srcA0 = X  + (size_t)(m0 + arow) * DIM + (tid & 1) * 16;
    const __half* srcB0 = Wt + (size_t)(n0 + arow) * DIM + (tid & 1) * 16;
    const uint32_t dstA0 = smbase + arow * (HSR * 2) + ab;

#define ISSUE(stage, ch) do {                                   \
        uint32_t dA = dstA0 + (stage) * STGB;                   \
        const __half* sA = srcA0 + (ch) * 32;                   \
        cp16(dA, sA); cp16(dA + 16, sA + 8);                    \
        uint32_t dB = dA + HABUF * 2;                           \
        const __half* sB = srcB0 + (ch) * 32;                   \
        cp16(dB, sB); cp16(dB + 16, sB + 8);                    \
    } while (0)

    ISSUE(0, 0); CP_COMMIT();
    ISSUE(1, 1); CP_COMMIT();

    const int NCHK = DIM / 32;   // 16
    for (int ch = 0; ch < NCHK; ch++) {
        CP_WAIT1();
        __syncthreads();
        if (ch + 2 < NCHK) {
            int st = ch + 2; st -= (st >= NSTG) ? NSTG : 0; st -= (st >= NSTG) ? NSTG : 0;
            // (ch+2)%3 computed cheaply:
            ISSUE((ch + 2) % NSTG, ch + 2);
        }
        CP_COMMIT();

        const uint32_t baseA = smbase + (ch % NSTG) * STGB;
        const uint32_t baseB = baseA + HABUF * 2;
#pragma unroll
        for (int ks = 0; ks < 2; ks++) {
            const int kc = ks * 16 + lcol;
            uint32_t af[2][4];
#pragma unroll
            for (int mt = 0; mt < 2; mt++)
                ldsm_x4(af[mt], baseA + ((warpM * 32 + mt * 16 + lrow) * HSR + kc) * 2);
#pragma unroll
            for (int ng = 0; ng < 4; ng++) {
                uint32_t bq[4];
                ldsm_x4(bq, baseB + ((warpN * 64 + ng * 16 + lrow) * HSR + kc) * 2);
#pragma unroll
                for (int mt = 0; mt < 2; mt++) {
                    mma_f16(c[mt][ng * 2],     af[mt], bq[0], bq[2]);
                    mma_f16(c[mt][ng * 2 + 1], af[mt], bq[1], bq[3]);
                }
            }
        }
    }
#undef ISSUE
}

// ---------------------------------------------------------------------------
// Fused a/b/g projections: z = blockIdx.z picks weight/bias/output/activation.
// Outputs fp16.
// ---------------------------------------------------------------------------
__global__ __launch_bounds__(256) void gemm3_h(
    const __half* __restrict__ X, const __half* __restrict__ Wth,
    const float* __restrict__ ba, const float* __restrict__ bbi,
    const float* __restrict__ bg,
    __half* __restrict__ Ca, __half* __restrict__ Cb, __half* __restrict__ Cg)
{
    extern __shared__ __half sm[];
    const int z = blockIdx.z;
    const __half* Wt = Wth + (size_t)z * DIM * DIM;
    const float* bias = (z == 0) ? ba : (z == 1) ? bbi : bg;
    __half* C = (z == 0) ? Ca : (z == 1) ? Cb : Cg;
    const int act = (z == 1) ? 0 : 1;
    const int m0 = blockIdx.y * 128;
    const int n0 = blockIdx.x * 128;

    float c[2][8][4];
#pragma unroll
    for (int mt = 0; mt < 2; mt++)
#pragma unroll
        for (int nt = 0; nt < 8; nt++)
#pragma unroll
            for (int r = 0; r < 4; r++) c[mt][nt][r] = 0.0f;

    gemm_mainloop(X, Wt, m0, n0, sm, c);

    const int lane = threadIdx.x & 31;
    const int wid  = threadIdx.x >> 5;
    const int g    = lane >> 2;
    const int t4   = lane & 3;
    const int warpM = wid & 3;
    const int warpN = wid >> 2;
#pragma unroll
    for (int mt = 0; mt < 2; mt++) {
#pragma unroll
        for (int nt = 0; nt < 8; nt++) {
            const int row  = m0 + warpM * 32 + mt * 16 + g;
            const int coln = n0 + warpN * 64 + nt * 8 + t4 * 2;
            const float b0 = bias[coln], b1 = bias[coln + 1];
            float v0 = c[mt][nt][0] + b0;
            float v1 = c[mt][nt][1] + b1;
            float v2 = c[mt][nt][2] + b0;
            float v3 = c[mt][nt][3] + b1;
            if (act) {
                v0 = 1.0f / (1.0f + __expf(-v0));
                v1 = 1.0f / (1.0f + __expf(-v1));
                v2 = 1.0f / (1.0f + __expf(-v2));
                v3 = 1.0f / (1.0f + __expf(-v3));
            }
            *(__half2*)&C[(size_t)row * DIM + coln]       = __floats2half2_rn(v0, v1);
            *(__half2*)&C[(size_t)(row + 8) * DIM + coln] = __floats2half2_rn(v2, v3);
        }
    }
}

// ---------------------------------------------------------------------------
// Final projection: out (f32) = hg @ Wo^T + bo
// ---------------------------------------------------------------------------
__global__ __launch_bounds__(256) void gemm1_f(
    const __half* __restrict__ X, const __half* __restrict__ Wt,
    const float* __restrict__ bias, float* __restrict__ C)
{
    extern __shared__ __half sm[];
    const int m0 = blockIdx.y * 128;
    const int n0 = blockIdx.x * 128;

    float c[2][8][4];
#pragma unroll
    for (int mt = 0; mt < 2; mt++)
#pragma unroll
        for (int nt = 0; nt < 8; nt++)
#pragma unroll
            for (int r = 0; r < 4; r++) c[mt][nt][r] = 0.0f;

    gemm_mainloop(X, Wt, m0, n0, sm, c);

    const int lane = threadIdx.x & 31;
    const int wid  = threadIdx.x >> 5;
    const int g    = lane >> 2;
    const int t4   = lane & 3;
    const int warpM = wid & 3;
    const int warpN = wid >> 2;
#pragma unroll
    for (int mt = 0; mt < 2; mt++) {
#pragma unroll
        for (int nt = 0; nt < 8; nt++) {
            const int row  = m0 + warpM * 32 + mt * 16 + g;
            const int coln = n0 + warpN * 64 + nt * 8 + t4 * 2;
            const float b0 = bias[coln], b1 = bias[coln + 1];
            *(float2*)&C[(size_t)row * DIM + coln] =
                make_float2(c[mt][nt][0] + b0, c[mt][nt][1] + b1);
            *(float2*)&C[(size_t)(row + 8) * DIM + coln] =
                make_float2(c[mt][nt][2] + b0, c[mt][nt][3] + b1);
        }
    }
}

// ---------------------------------------------------------------------------
// Chunked linear scan (fp16 storage, fp32 math, half2 vectorized)
// ---------------------------------------------------------------------------
__global__ __launch_bounds__(256) void scan_chunks_h()
{
    const int d2 = threadIdx.x;            // half2 index 0..255
    const int c  = blockIdx.x;
    const int bb = blockIdx.y;
    const __half2* pa = (const __half2*)g_ah;
    const __half2* pb = (const __half2*)g_bh;
    size_t base = ((size_t)(bb * TT + c * CHUNK) * DIM) / 2 + d2;
    float A0 = 1.0f, A1 = 1.0f, h0 = 0.0f, h1 = 0.0f;
#pragma unroll 4
    for (int t = 0; t < CHUNK; t++) {
        float2 af = __half22float2(pa[base + (size_t)t * 256]);
        float2 bf = __half22float2(pb[base + (size_t)t * 256]);
        h0 = fmaf(af.x, h0, bf.x);
        h1 = fmaf(af.y, h1, bf.y);
        A0 *= af.x; A1 *= af.y;
    }
    const int idx = (bb * NCH + c) * DIM + 2 * d2;
    g_cA[idx] = A0; g_cA[idx + 1] = A1;
    g_cB[idx] = h0; g_cB[idx + 1] = h1;
}

__global__ __launch_bounds__(512) void scan_carry()
{
    const int d  = threadIdx.x;
    const int bb = blockIdx.x;
    float h = 0.0f;
#pragma unroll
    for (int c = 0; c < NCH; c++) {
        const int idx = (bb * NCH + c) * DIM + d;
        g_pref[idx] = h;
        h = fmaf(g_cA[idx], h, g_cB[idx]);
    }
}

__global__ __launch_bounds__(256) void scan_apply_h()
{
    const int d2 = threadIdx.x;
    const int c  = blockIdx.x;
    const int bb = blockIdx.y;
    const __half2* pa = (const __half2*)g_ah;
    const __half2* pb = (const __half2*)g_bh;
    const __half2* pg = (const __half2*)g_gh;
    __half2* phg = (__half2*)g_hgh;
    size_t base = ((size_t)(bb * TT + c * CHUNK) * DIM) / 2 + d2;
    float2 pf = *(float2*)&g_pref[(bb * NCH + c) * DIM + 2 * d2];
    float h0 = pf.x, h1 = pf.y;
#pragma unroll 4
    for (int t = 0; t < CHUNK; t++) {
        float2 af = __half22float2(pa[base + (size_t)t * 256]);
        float2 bf = __half22float2(pb[base + (size_t)t * 256]);
        float2 gf = __half22float2(pg[base + (size_t)t * 256]);
        h0 = fmaf(af.x, h0, bf.x);
        h1 = fmaf(af.y, h1, bf.y);
        phg[base + (size_t)t * 256] = __floats2half2_rn(h0 * gf.x, h1 * gf.y);
    }
}

// ---------------------------------------------------------------------------
// Retention via fp16 mma.sync (windowed, WIN=256) — unchanged from R5
// ---------------------------------------------------------------------------
#define SR   36
#define SRV  38

__device__ __forceinline__ uint32_t packh2(float lo, float hi) {
    __half2 h = __floats2half2_rn(lo, hi);
    return *(uint32_t*)&h;
}

__global__ __launch_bounds__(256) void retention_mma(
    const float* __restrict__ q, const float* __restrict__ k,
    const float* __restrict__ v, float* __restrict__ out)
{
    __shared__ uint32_t Qs[64 * SR];
    __shared__ uint32_t Ks[64 * SR];
    __shared__ uint32_t Ss[64 * SR];
    __shared__ uint32_t Vt[64 * SRV];

    const int tid  = threadIdx.x;
    const int lane = tid & 31;
    const int wid  = tid >> 5;
    const int g    = lane >> 2;
    const int t4   = lane & 3;
    const int tb   = (wid & 3) * 16;
    const int nb   = (wid >> 2) * 32;

    const int t0 = blockIdx.x * TBLK;
    const int hh = blockIdx.y;
    const int bb = blockIdx.z;

    const float* qb = q + (size_t)bb * TT * DIM + hh * DH;
    const float* kb = k + (size_t)bb * TT * DIM + hh * DH;
    const float* vb = v + (size_t)bb * TT * DIM + hh * DH;

    const int row = tid >> 2;
    const int dg  = (tid & 3) * 16;
    const int vd0 = (tid & 15) * 4;
    const int vs0 = (tid >> 4) * 4;

    {
        const float4* qrow = (const float4*)&qb[(size_t)(t0 + row) * DIM + dg];
        uint32_t tmp[8];
#pragma unroll
        for (int i = 0; i < 4; i++) {
            float4 x = qrow[i];
            tmp[2*i]   = packh2(x.x, x.y);
            tmp[2*i+1] = packh2(x.z, x.w);
        }
        *(uint4*)&Qs[row * SR + (tid & 3) * 8]     = make_uint4(tmp[0], tmp[1], tmp[2], tmp[3]);
        *(uint4*)&Qs[row * SR + (tid & 3) * 8 + 4] = make_uint4(tmp[4], tmp[5], tmp[6], tmp[7]);
    }
    __syncthreads();

    uint32_t afq[4][4];
#pragma unroll
    for (int kk = 0; kk < 4; kk++) {
        afq[kk][0] = Qs[(tb + g)     * SR + kk * 8 + t4];
        afq[kk][1] = Qs[(tb + g + 8) * SR + kk * 8 + t4];
        afq[kk][2] = Qs[(tb + g)     * SR + kk * 8 + t4 + 4];
        afq[kk][3] = Qs[(tb + g + 8) * SR + kk * 8 + t4 + 4];
    }

    float dsv[4][2];
    dsv[0][0] = exp2f(-L2DECAY * (float)(nb + 2 * t4));
    dsv[0][1] = dsv[0][0] * DINV;
#pragma unroll
    for (int nf = 1; nf < 4; nf++) {
        dsv[nf][0] = dsv[nf-1][0] * DM8INV;
        dsv[nf][1] = dsv[nf-1][1] * DM8INV;
    }

    float co[4][4];
#pragma unroll
    for (int nf = 0; nf < 4; nf++)
#pragma unroll
        for (int r = 0; r < 4; r++) co[nf][r] = 0.0f;

    const int sBeg = (t0 >= WIN) ? (t0 - WIN) : 0;

    for (int s0 = sBeg; s0 <= t0; s0 += SCH) {
        float4 kx[4], vx[4];
        {
            const float4* krow = (const float4*)&kb[(size_t)(s0 + row) * DIM + dg];
#pragma unroll
            for (int i = 0; i < 4; i++) kx[i] = krow[i];
#pragma unroll
            for (int i = 0; i < 4; i++)
                vx[i] = *(const float4*)&vb[(size_t)(s0 + vs0 + i) * DIM + vd0];
        }
        __syncthreads();

        {
            uint32_t tmp[8];
#pragma unroll
            for (int i = 0; i < 4; i++) {
                tmp[2*i]   = packh2(kx[i].x, kx[i].y);
                tmp[2*i+1] = packh2(kx[i].z, kx[i].w);
            }
            *(uint4*)&Ks[row * SR + (tid & 3) * 8]     = make_uint4(tmp[0], tmp[1], tmp[2], tmp[3]);
            *(uint4*)&Ks[row * SR + (tid & 3) * 8 + 4] = make_uint4(tmp[4], tmp[5], tmp[6], tmp[7]);
        }
        {
            const float vr[4][4] = {
                {vx[0].x, vx[0].y, vx[0].z, vx[0].w},
                {vx[1].x, vx[1].y, vx[1].z, vx[1].w},
                {vx[2].x, vx[2].y, vx[2].z, vx[2].w},
                {vx[3].x, vx[3].y, vx[3].z, vx[3].w}};
#pragma unroll
            for (int j = 0; j < 4; j++) {
                Vt[(vd0 + j) * SRV + (vs0 >> 1)]     = packh2(vr[0][j], vr[1][j]);
                Vt[(vd0 + j) * SRV + (vs0 >> 1) + 1] = packh2(vr[2][j], vr[3][j]);
            }
        }
        __syncthreads();

        float cs[4][4];
#pragma unroll
        for (int nf = 0; nf < 4; nf++)
#pragma unroll
            for (int r = 0; r < 4; r++) cs[nf][r] = 0.0f;
#pragma unroll
        for (int kk = 0; kk < 4; kk++) {
#pragma unroll
            for (int nf = 0; nf < 4; nf++) {
                const int rn = (nb + nf * 8 + g) * SR + kk * 8 + t4;
                mma_f16(cs[nf], afq[kk], Ks[rn], Ks[rn + 4]);
            }
        }

        const int off = t0 - s0;
        const float Dt0 = exp2f((float)(tb + g + off) * L2DECAY);
        const float Dt1 = Dt0 * D8;
#pragma unroll
        for (int nf = 0; nf < 4; nf++) {
            const int scol = nb + nf * 8 + 2 * t4;
            const int d0 = tb + g + off - scol;
            float w00 = (d0     >= 0) ? Dt0 * dsv[nf][0] : 0.0f;
            float w01 = (d0 - 1 >= 0) ? Dt0 * dsv[nf][1] : 0.0f;
            float w10 = (d0 + 8 >= 0) ? Dt1 * dsv[nf][0] : 0.0f;
            float w11 = (d0 + 7 >= 0) ? Dt1 * dsv[nf][1] : 0.0f;
            Ss[(tb + g)     * SR + (nb >> 1) + nf * 4 + t4] = packh2(cs[nf][0] * w00, cs[nf][1] * w01);
            Ss[(tb + g + 8) * SR + (nb >> 1) + nf * 4 + t4] = packh2(cs[nf][2] * w10, cs[nf][3] * w11);
        }
        __syncthreads();

#pragma unroll
        for (int kk = 0; kk < 4; kk++) {
            uint32_t as[4];
            as[0] = Ss[(tb + g)     * SR + kk * 8 + t4];
            as[1] = Ss[(tb + g + 8) * SR + kk * 8 + t4];
            as[2] = Ss[(tb + g)     * SR + kk * 8 + t4 + 4];
            as[3] = Ss[(tb + g + 8) * SR + kk * 8 + t4 + 4];
#pragma unroll
            for (int nf = 0; nf < 4; nf++) {
                const int rn = (nb + nf * 8 + g) * SRV + kk * 8 + t4;
                mma_f16(co[nf], as, Vt[rn], Vt[rn + 4]);
            }
        }
    }

#pragma unroll
    for (int nf = 0; nf < 4; nf++) {
        const int col = hh * DH + nb + nf * 8 + 2 * t4;
        float2* p0 = (float2*)&out[((size_t)bb * TT + t0 + tb + g)     * DIM + col];
        float2* p1 = (float2*)&out[((size_t)bb * TT + t0 + tb + g + 8) * DIM + col];
        float2 o0 = *p0, o1 = *p1;
        o0.x += co[nf][0]; o0.y += co[nf][1];
        o1.x += co[nf][2]; o1.y += co[nf][3];
        *p0 = o0; *p1 = o1;
    }
}

// ---------------------------------------------------------------------------
extern "C" void kernel_launch(void* const* d_in, const int* in_sizes, int n_in,
                              void* d_out, int out_size)
{
    const float* q  = (const float*)d_in[0];
    const float* k  = (const float*)d_in[1];
    const float* v  = (const float*)d_in[2];
    const float* Wa = (const float*)d_in[3];
    const float* ba = (const float*)d_in[4];
    const float* Wb = (const float*)d_in[5];
    const float* bb = (const float*)d_in[6];
    const float* Wg = (const float*)d_in[7];
    const float* bg = (const float*)d_in[8];
    const float* Wo = (const float*)d_in[9];
    const float* bo = (const float*)d_in[10];
    float* out = (float*)d_out;

    __half *pah, *pbh, *pgh, *phgh, *pqh, *pwth;
    cudaGetSymbolAddress((void**)&pah,  g_ah);
    cudaGetSymbolAddress((void**)&pbh,  g_bh);
    cudaGetSymbolAddress((void**)&pgh,  g_gh);
    cudaGetSymbolAddress((void**)&phgh, g_hgh);
    cudaGetSymbolAddress((void**)&pqh,  g_qh);
    cudaGetSymbolAddress((void**)&pwth, g_Wth);

    cudaFuncSetAttribute(gemm3_h, cudaFuncAttributeMaxDynamicSharedMemorySize, PIPE_SMEM);
    cudaFuncSetAttribute(gemm1_f, cudaFuncAttributeMaxDynamicSharedMemorySize, PIPE_SMEM);

    transposeW4h<<<dim3(DIM / 32, DIM / 32, 4), dim3(32, 8)>>>(Wa, Wb, Wg, Wo, pwth);
    f2h_bulk<<<(MROWS * DIM) / (256 * 8), 256>>>(q, pqh);

    gemm3_h<<<dim3(DIM / 128, MROWS / 128, 3), 256, PIPE_SMEM>>>(
        pqh, pwth, ba, bb, bg, pah, pbh, pgh);

    scan_chunks_h<<<dim3(NCH, BB), 256>>>();
    scan_carry<<<BB, 512>>>();
    scan_apply_h<<<dim3(NCH, BB), 256>>>();

    gemm1_f<<<dim3(DIM / 128, MROWS / 128, 1), 256, PIPE_SMEM>>>(
        phgh, pwth + 3 * DIM * DIM, bo, out);

    retention_mma<<<dim3(TT / TBLK, NH, BB), 256>>>(q, k, v, out);
}